// round 2
// baseline (speedup 1.0000x reference)
#include <cuda_runtime.h>
#include <math.h>
#include <stdint.h>

#define NN  2048
#define TT  64
#define EE  16384
#define BB  64
#define C0  32
#define EMB 128
#define C1  64
#define C2  64
#define EPSB 1e-5f

// ---------------- scratch (device globals; no allocation allowed) ----------------
__device__ float d_h1[NN*TT*C0];     // conv1 out (16MB)
__device__ float d_a1[NN*TT*C0];     // agg1 out  (16MB)
__device__ float d_h2[NN*TT*EMB];    // gcn1 out, later gcn2 out (64MB)
__device__ float d_a2[NN*TT*EMB];    // agg2 out  (64MB)
__device__ float d_pool[NN*14*C1];   // fused conv2 out (7MB)
__device__ float d_gp[BB*14*C1];
__device__ float d_counts[BB];
__device__ int   d_rowcnt[NN];
__device__ int   d_rowstart[NN+1];
__device__ int   d_cursor[NN];
__device__ int   d_csrsrc[EE];
__device__ float d_dinv[NN];
__device__ float d_weff2[10*EMB*C1]; // pooled-collapsed conv2 weights (bn2 scale folded)
__device__ float d_beff2[C1];
__device__ float d_weff3[10*C2*C2];
__device__ float d_beff3[C2];
__device__ float d_s1[C0];
__device__ float d_b1e[C0];

__device__ __forceinline__ float to_tf32(float x) {
    float r;
    asm("cvt.rna.tf32.f32 %0, %1;" : "=f"(r) : "f"(x));
    return r;
}

// ---------------- 0: zero accumulators ----------------
__global__ void k_zero() {
    int i = blockIdx.x * blockDim.x + threadIdx.x;
    if (i < BB*14*C1) d_gp[i] = 0.f;
    if (i < NN)       d_rowcnt[i] = 0;
    if (i < BB)       d_counts[i] = 0.f;
}

// ---------------- 1: prep (degree count, batch count, folded weights) ----------------
__global__ void k_prep(const int* __restrict__ edge, const int* __restrict__ batch,
                       const float* __restrict__ g1, const float* __restrict__ b1,
                       const float* __restrict__ m1, const float* __restrict__ v1,
                       const float* __restrict__ w2, const float* __restrict__ g2,
                       const float* __restrict__ b2, const float* __restrict__ m2,
                       const float* __restrict__ v2,
                       const float* __restrict__ w3, const float* __restrict__ g3,
                       const float* __restrict__ b3, const float* __restrict__ m3,
                       const float* __restrict__ v3) {
    int i = blockIdx.x * blockDim.x + threadIdx.x;
    if (i < EE) atomicAdd(&d_rowcnt[edge[EE + i]], 1);
    if (i < NN) atomicAdd(&d_counts[batch[i]], 1.0f);
    if (i < C0) { float s = g1[i]*rsqrtf(v1[i]+EPSB); d_s1[i]=s; d_b1e[i]=b1[i]-m1[i]*s; }
    if (i < C1) { float s = g2[i]*rsqrtf(v2[i]+EPSB); d_beff2[i]=b2[i]-m2[i]*s; }
    if (i < C2) { float s = g3[i]*rsqrtf(v3[i]+EPSB); d_beff3[i]=b3[i]-m3[i]*s; }
    if (i < 10*EMB*C1) {
        int c = i % C1; int ci = (i / C1) % EMB; int u = i / (C1*EMB);
        float s = g2[c]*rsqrtf(v2[c]+EPSB);
        int klo = u-3; if (klo < 0) klo = 0;
        int khi = u < 6 ? u : 6;
        float acc = 0.f;
        for (int k = klo; k <= khi; k++) acc += w2[(k*EMB+ci)*C1 + c];
        d_weff2[i] = acc * s * 0.25f;
    }
    if (i < 10*C2*C2) {
        int c = i % C2; int ci = (i / C2) % C2; int u = i / (C2*C2);
        float s = g3[c]*rsqrtf(v3[c]+EPSB);
        int klo = u-3; if (klo < 0) klo = 0;
        int khi = u < 6 ? u : 6;
        float acc = 0.f;
        for (int k = klo; k <= khi; k++) acc += w3[(k*C2+ci)*C2 + c];
        d_weff3[i] = acc * s * 0.25f;
    }
}

// ---------------- 2: prefix scan -> CSR row starts, dinv ----------------
__global__ void k_scan() {
    __shared__ int sa[NN], sb[NN];
    int t = threadIdx.x;                       // 1024 threads
    sa[t] = d_rowcnt[t]; sa[t+1024] = d_rowcnt[t+1024];
    __syncthreads();
    int* cur = sa; int* nxt = sb;
    for (int off = 1; off < NN; off <<= 1) {
        for (int j = t; j < NN; j += 1024) {
            int v = cur[j];
            if (j >= off) v += cur[j-off];
            nxt[j] = v;
        }
        __syncthreads();
        int* tmp = cur; cur = nxt; nxt = tmp;
    }
    for (int j = t; j < NN; j += 1024) {
        int excl = (j == 0) ? 0 : cur[j-1];
        d_rowstart[j] = excl;
        d_cursor[j]   = excl;
        d_dinv[j]     = rsqrtf((float)(d_rowcnt[j] + 1));
        if (j == NN-1) d_rowstart[NN] = cur[NN-1];
    }
}

// ---------------- 3: scatter edges into CSR ----------------
__global__ void k_scatter(const int* __restrict__ edge) {
    int e = blockIdx.x * blockDim.x + threadIdx.x;
    if (e < EE) {
        int dd = edge[EE + e];
        int pos = atomicAdd(&d_cursor[dd], 1);
        d_csrsrc[pos] = edge[e];
    }
}

// ---------------- 4: conv1 + bn1 + relu: (N,T) -> (N,T,32) ----------------
__global__ void k_conv1(const float* __restrict__ x, const float* __restrict__ w) {
    __shared__ float xs[TT];
    __shared__ float ws[7*C0];
    __shared__ float ss[C0], bs[C0];
    int n = blockIdx.x, tid = threadIdx.x;     // 256 threads
    if (tid < TT)   xs[tid] = x[n*TT + tid];
    if (tid < 7*C0) ws[tid] = w[tid];
    if (tid < C0) { ss[tid] = d_s1[tid]; bs[tid] = d_b1e[tid]; }
    __syncthreads();
    int c = tid & 31, t0 = tid >> 5;
    for (int t = t0; t < TT; t += 8) {
        float acc = 0.f;
        #pragma unroll
        for (int k = 0; k < 7; k++) {
            int ti = t + k - 3;
            if (ti >= 0 && ti < TT) acc += xs[ti] * ws[k*C0 + c];
        }
        acc = acc * ss[c] + bs[c];
        d_h1[(n*TT + t)*C0 + c] = fmaxf(acc, 0.f);
    }
}

// ---------------- 5/7: CSR aggregation  out[i] = sum_j norm_ij * in[j] ----------------
__global__ void k_agg1() {           // rows of 2048 floats (h1 -> a1)
    int node = blockIdx.x;
    int off  = threadIdx.x * 4;      // 256 threads * 4, plus +1024
    float di = d_dinv[node];
    float w  = di * di;
    const float* base = d_h1 + (size_t)node*2048 + off;
    float4 v0 = *(const float4*)base;
    float4 v1 = *(const float4*)(base + 1024);
    float4 a0 = make_float4(v0.x*w, v0.y*w, v0.z*w, v0.w*w);
    float4 a1 = make_float4(v1.x*w, v1.y*w, v1.z*w, v1.w*w);
    int e0 = d_rowstart[node], e1 = d_rowstart[node+1];
    for (int e = e0; e < e1; e++) {
        int s = d_csrsrc[e];
        float ww = di * d_dinv[s];
        const float* sb = d_h1 + (size_t)s*2048 + off;
        float4 u0 = *(const float4*)sb;
        float4 u1 = *(const float4*)(sb + 1024);
        a0.x += ww*u0.x; a0.y += ww*u0.y; a0.z += ww*u0.z; a0.w += ww*u0.w;
        a1.x += ww*u1.x; a1.y += ww*u1.y; a1.z += ww*u1.z; a1.w += ww*u1.w;
    }
    float* ob = d_a1 + (size_t)node*2048 + off;
    *(float4*)ob = a0;
    *(float4*)(ob + 1024) = a1;
}

__global__ void k_agg2() {           // rows of 8192 floats (h2 -> a2), grid.y = 4 chunks
    int node = blockIdx.x;
    int off  = blockIdx.y*2048 + threadIdx.x*4;
    float di = d_dinv[node];
    float w  = di * di;
    const float* base = d_h2 + (size_t)node*8192 + off;
    float4 v0 = *(const float4*)base;
    float4 v1 = *(const float4*)(base + 1024);
    float4 a0 = make_float4(v0.x*w, v0.y*w, v0.z*w, v0.w*w);
    float4 a1 = make_float4(v1.x*w, v1.y*w, v1.z*w, v1.w*w);
    int e0 = d_rowstart[node], e1 = d_rowstart[node+1];
    for (int e = e0; e < e1; e++) {
        int s = d_csrsrc[e];
        float ww = di * d_dinv[s];
        const float* sb = d_h2 + (size_t)s*8192 + off;
        float4 u0 = *(const float4*)sb;
        float4 u1 = *(const float4*)(sb + 1024);
        a0.x += ww*u0.x; a0.y += ww*u0.y; a0.z += ww*u0.z; a0.w += ww*u0.w;
        a1.x += ww*u1.x; a1.y += ww*u1.y; a1.z += ww*u1.z; a1.w += ww*u1.w;
    }
    float* ob = d_a2 + (size_t)node*8192 + off;
    *(float4*)ob = a0;
    *(float4*)(ob + 1024) = a1;
}

// ---------------- 6: gcn1 matmul (131072,32)@(32,128) + bias + relu ----------------
__global__ void k_mm1(const float* __restrict__ W, const float* __restrict__ bias) {
    __shared__ float Ws[C0*EMB];   // 16KB
    __shared__ float As[64*C0];    // 8KB
    int tid = threadIdx.x;         // 256
    for (int i = tid; i < C0*EMB; i += 256) Ws[i] = W[i];
    int rowbase = blockIdx.x * 64;
    for (int i = tid; i < 64*C0; i += 256) As[i] = d_a1[(size_t)rowbase*C0 + i];
    __syncthreads();
    int c = tid & 127, rh = tid >> 7;
    float wreg[C0];
    #pragma unroll
    for (int k = 0; k < C0; k++) wreg[k] = Ws[k*EMB + c];
    float b = bias[c];
    for (int rr = 0; rr < 32; rr++) {
        const float* ap = &As[(rh*32 + rr)*C0];
        float acc = b;
        #pragma unroll
        for (int k = 0; k < C0; k += 4) {
            float4 a = *(const float4*)(ap + k);
            acc += a.x*wreg[k] + a.y*wreg[k+1] + a.z*wreg[k+2] + a.w*wreg[k+3];
        }
        d_h2[(size_t)(rowbase + rh*32 + rr)*EMB + c] = fmaxf(acc, 0.f);
    }
}

// ---------------- 8: gcn2 matmul via tf32 mma.sync: (131072,128)@(128,128)+bias+relu ----
// Block: 128 rows x 128 cols, 256 threads (8 warps x 16 rows). K in 4 chunks of 32.
__global__ void __launch_bounds__(256) k_mm2_tc(const float* __restrict__ W,
                                               const float* __restrict__ bias) {
    __shared__ float As[128*36];   // padded ld=36 -> conflict-free frag loads
    __shared__ float Bs[32*132];   // padded ld=132 -> <=2-way
    int tid = threadIdx.x;
    int wid = tid >> 5, lane = tid & 31;
    int g = lane >> 2, tg = lane & 3;      // groupID, threadID_in_group
    int rowbase = blockIdx.x * 128;
    int mrow = wid * 16;

    float acc[16][4];
    #pragma unroll
    for (int nt = 0; nt < 16; nt++) {
        int c = nt*8 + 2*tg;
        float b0 = bias[c], b1 = bias[c+1];
        acc[nt][0] = b0; acc[nt][1] = b1; acc[nt][2] = b0; acc[nt][3] = b1;
    }

    for (int kc = 0; kc < 4; kc++) {
        // load A chunk: 128 rows x 32 k
        #pragma unroll
        for (int i = tid; i < 1024; i += 256) {
            int r = i >> 3, k4 = (i & 7) * 4;
            float4 v = *(const float4*)&d_a2[(size_t)(rowbase + r)*EMB + kc*32 + k4];
            v.x = to_tf32(v.x); v.y = to_tf32(v.y); v.z = to_tf32(v.z); v.w = to_tf32(v.w);
            *(float4*)&As[r*36 + k4] = v;
        }
        // load B chunk: 32 k x 128 n
        #pragma unroll
        for (int i = tid; i < 1024; i += 256) {
            int k = i >> 5, n4 = (i & 31) * 4;
            float4 v = *(const float4*)&W[(size_t)(kc*32 + k)*EMB + n4];
            v.x = to_tf32(v.x); v.y = to_tf32(v.y); v.z = to_tf32(v.z); v.w = to_tf32(v.w);
            *(float4*)&Bs[k*132 + n4] = v;
        }
        __syncthreads();
        #pragma unroll
        for (int ks = 0; ks < 4; ks++) {
            int kb = ks * 8;
            uint32_t a0 = __float_as_uint(As[(mrow+g  )*36 + kb + tg]);
            uint32_t a1 = __float_as_uint(As[(mrow+g+8)*36 + kb + tg]);
            uint32_t a2 = __float_as_uint(As[(mrow+g  )*36 + kb + tg + 4]);
            uint32_t a3 = __float_as_uint(As[(mrow+g+8)*36 + kb + tg + 4]);
            #pragma unroll
            for (int nt = 0; nt < 16; nt++) {
                uint32_t b0 = __float_as_uint(Bs[(kb+tg  )*132 + nt*8 + g]);
                uint32_t b1 = __float_as_uint(Bs[(kb+tg+4)*132 + nt*8 + g]);
                asm volatile(
                    "mma.sync.aligned.m16n8k8.row.col.f32.tf32.tf32.f32 "
                    "{%0,%1,%2,%3}, {%4,%5,%6,%7}, {%8,%9}, {%0,%1,%2,%3};"
                    : "+f"(acc[nt][0]), "+f"(acc[nt][1]), "+f"(acc[nt][2]), "+f"(acc[nt][3])
                    : "r"(a0), "r"(a1), "r"(a2), "r"(a3), "r"(b0), "r"(b1));
            }
        }
        __syncthreads();
    }

    int row0 = rowbase + mrow + g;
    int row1 = row0 + 8;
    #pragma unroll
    for (int nt = 0; nt < 16; nt++) {
        int c = nt*8 + 2*tg;
        *(float2*)&d_h2[(size_t)row0*EMB + c] =
            make_float2(fmaxf(acc[nt][0], 0.f), fmaxf(acc[nt][1], 0.f));
        *(float2*)&d_h2[(size_t)row1*EMB + c] =
            make_float2(fmaxf(acc[nt][2], 0.f), fmaxf(acc[nt][3], 0.f));
    }
}

// ---------------- 9: fused conv2+bn2+avgpool+relu: (N,64,128) -> (N,14,64) ----------------
// 112 threads = 14 p-slots x 8 c-groups; 8 channels per thread; weights streamed
// from global (L1/L2-hot, 327KB).
__global__ void __launch_bounds__(112) k_conv2() {
    __shared__ float hs[62*132];   // ld=132 pad
    int n = blockIdx.x, tid = threadIdx.x;      // 112 threads
    for (int i = tid; i < 62*32; i += 112) {
        int t = i >> 5, k4 = (i & 31) * 4;
        *(float4*)&hs[t*132 + k4] = *(const float4*)&d_h2[(size_t)n*TT*EMB + t*EMB + k4];
    }
    __syncthreads();
    int p = tid >> 3, cg = tid & 7;
    float acc[8];
    #pragma unroll
    for (int j = 0; j < 8; j++) acc[j] = d_beff2[cg*8 + j];
    for (int u = 0; u < 10; u++) {
        const float* wbase = &d_weff2[u*EMB*C1 + cg*8];
        const float* hb = &hs[(4*p + u)*132];
        #pragma unroll 4
        for (int ci = 0; ci < 128; ci++) {
            float hv = hb[ci];
            float4 w0 = *(const float4*)(wbase + ci*C1);
            float4 w1 = *(const float4*)(wbase + ci*C1 + 4);
            acc[0] += hv*w0.x; acc[1] += hv*w0.y; acc[2] += hv*w0.z; acc[3] += hv*w0.w;
            acc[4] += hv*w1.x; acc[5] += hv*w1.y; acc[6] += hv*w1.z; acc[7] += hv*w1.w;
        }
    }
    size_t ob = (size_t)n*14*C1 + p*C1 + cg*8;
    #pragma unroll
    for (int j = 0; j < 8; j++) d_pool[ob + j] = fmaxf(acc[j], 0.f);
}

// ---------------- 10: graph sum pool (atomic) ----------------
__global__ void k_gpool(const int* __restrict__ batch) {
    int i = blockIdx.x * blockDim.x + threadIdx.x;
    if (i < NN*14*C1) {
        int n = i / (14*C1);
        int rem = i - n*14*C1;
        atomicAdd(&d_gp[batch[n]*14*C1 + rem], d_pool[i]);
    }
}

// ---------------- 11: conv3+bn3+pool+relu + dense + log_softmax ----------------
__global__ void k_final(const float* __restrict__ dw, const float* __restrict__ db,
                        float* __restrict__ out) {
    __shared__ float gin[14*C1];
    __shared__ float flat[128];
    __shared__ float lg[4];
    int b = blockIdx.x, tid = threadIdx.x;     // 128 threads
    float inv = 1.f / d_counts[b];
    for (int i = tid; i < 14*C1; i += 128) gin[i] = d_gp[b*14*C1 + i] * inv;
    __syncthreads();
    int p = tid >> 6, c = tid & 63;
    float acc = d_beff3[c];
    for (int u = 0; u < 10; u++)
        for (int ci = 0; ci < C2; ci++)
            acc += gin[(4*p + u)*C2 + ci] * d_weff3[(u*C2 + ci)*C2 + c];
    flat[p*64 + c] = fmaxf(acc, 0.f);
    __syncthreads();
    if (tid < 4) {
        float a = db[tid];
        for (int i = 0; i < 128; i++) a += flat[i] * dw[i*4 + tid];
        lg[tid] = a;
    }
    __syncthreads();
    if (tid == 0) {
        float m = fmaxf(fmaxf(lg[0], lg[1]), fmaxf(lg[2], lg[3]));
        float se = expf(lg[0]-m) + expf(lg[1]-m) + expf(lg[2]-m) + expf(lg[3]-m);
        float lse = logf(se) + m;
        for (int j = 0; j < 4; j++) out[b*4 + j] = lg[j] - lse;
    }
}

// ---------------- launcher ----------------
extern "C" void kernel_launch(void* const* d_in, const int* in_sizes, int n_in,
                              void* d_out, int out_size) {
    const float* x       = (const float*)d_in[0];
    const int*   edge    = (const int*)d_in[1];
    const int*   batch   = (const int*)d_in[2];
    const float* conv1_w = (const float*)d_in[3];
    const float* bn1_g   = (const float*)d_in[4];
    const float* bn1_b   = (const float*)d_in[5];
    const float* bn1_m   = (const float*)d_in[6];
    const float* bn1_v   = (const float*)d_in[7];
    const float* gcn1_w  = (const float*)d_in[8];
    const float* gcn1_b  = (const float*)d_in[9];
    const float* gcn2_w  = (const float*)d_in[10];
    const float* gcn2_b  = (const float*)d_in[11];
    const float* conv2_w = (const float*)d_in[12];
    const float* bn2_g   = (const float*)d_in[13];
    const float* bn2_b   = (const float*)d_in[14];
    const float* bn2_m   = (const float*)d_in[15];
    const float* bn2_v   = (const float*)d_in[16];
    const float* conv3_w = (const float*)d_in[17];
    const float* bn3_g   = (const float*)d_in[18];
    const float* bn3_b   = (const float*)d_in[19];
    const float* bn3_m   = (const float*)d_in[20];
    const float* bn3_v   = (const float*)d_in[21];
    const float* dense_w = (const float*)d_in[22];
    const float* dense_b = (const float*)d_in[23];
    float* out = (float*)d_out;

    k_zero<<<224, 256>>>();
    k_prep<<<320, 256>>>(edge, batch, bn1_g, bn1_b, bn1_m, bn1_v,
                         conv2_w, bn2_g, bn2_b, bn2_m, bn2_v,
                         conv3_w, bn3_g, bn3_b, bn3_m, bn3_v);
    k_scan<<<1, 1024>>>();
    k_scatter<<<64, 256>>>(edge);
    k_conv1<<<NN, 256>>>(x, conv1_w);
    k_agg1<<<NN, 256>>>();
    k_mm1<<<NN, 256>>>(gcn1_w, gcn1_b);
    k_agg2<<<dim3(NN, 4), 256>>>();
    k_mm2_tc<<<1024, 256>>>(gcn2_w, gcn2_b);
    k_conv2<<<NN, 112>>>();
    k_gpool<<<7168, 256>>>(batch);
    k_final<<<BB, 128>>>(dense_w, dense_b, out);
}

// round 3
// speedup vs baseline: 2.9040x; 2.9040x over previous
#include <cuda_runtime.h>
#include <math.h>
#include <stdint.h>

#define NN  2048
#define TT  64
#define EE  16384
#define BB  64
#define C0  32
#define EMB 128
#define C1  64
#define C2  64
#define EPSB 1e-5f

// ---------------- scratch (device globals; no allocation allowed) ----------------
__device__ float d_h1[NN*TT*C0];     // conv1 out (16MB)
__device__ float d_a1[NN*TT*C0];     // agg1 out  (16MB)
__device__ float d_h2[NN*TT*EMB];    // gcn1 out, later gcn2 out (64MB)
__device__ float d_a2[NN*TT*EMB];    // agg2 out  (64MB)
__device__ float d_pool[NN*14*C1];   // fused conv2 out (7MB)
__device__ float d_gp[BB*14*C1];
__device__ float d_counts[BB];
__device__ int   d_rowcnt[NN];
__device__ int   d_rowstart[NN+1];
__device__ int   d_cursor[NN];
__device__ int   d_csrsrc[EE];
__device__ float d_dinv[NN];
__device__ float d_weff2[10*EMB*C1]; // pooled-collapsed conv2 weights (bn2 scale folded)
__device__ float d_beff2[C1];
__device__ float d_weff3[10*C2*C2];
__device__ float d_beff3[C2];
__device__ float d_s1[C0];
__device__ float d_b1e[C0];

__device__ __forceinline__ float to_tf32(float x) {
    float r;
    asm("cvt.rna.tf32.f32 %0, %1;" : "=f"(r) : "f"(x));
    return r;
}
__device__ __forceinline__ float4 to_tf32_4(float4 v) {
    v.x = to_tf32(v.x); v.y = to_tf32(v.y); v.z = to_tf32(v.z); v.w = to_tf32(v.w);
    return v;
}

// ---------------- 0: zero accumulators ----------------
__global__ void k_zero() {
    int i = blockIdx.x * blockDim.x + threadIdx.x;
    if (i < BB*14*C1) d_gp[i] = 0.f;
    if (i < NN)       d_rowcnt[i] = 0;
    if (i < BB)       d_counts[i] = 0.f;
}

// ---------------- 1: prep (degree count, batch count, folded weights) ----------------
__global__ void k_prep(const int* __restrict__ edge, const int* __restrict__ batch,
                       const float* __restrict__ g1, const float* __restrict__ b1,
                       const float* __restrict__ m1, const float* __restrict__ v1,
                       const float* __restrict__ w2, const float* __restrict__ g2,
                       const float* __restrict__ b2, const float* __restrict__ m2,
                       const float* __restrict__ v2,
                       const float* __restrict__ w3, const float* __restrict__ g3,
                       const float* __restrict__ b3, const float* __restrict__ m3,
                       const float* __restrict__ v3) {
    int i = blockIdx.x * blockDim.x + threadIdx.x;
    if (i < EE) atomicAdd(&d_rowcnt[edge[EE + i]], 1);
    if (i < NN) atomicAdd(&d_counts[batch[i]], 1.0f);
    if (i < C0) { float s = g1[i]*rsqrtf(v1[i]+EPSB); d_s1[i]=s; d_b1e[i]=b1[i]-m1[i]*s; }
    if (i < C1) { float s = g2[i]*rsqrtf(v2[i]+EPSB); d_beff2[i]=b2[i]-m2[i]*s; }
    if (i < C2) { float s = g3[i]*rsqrtf(v3[i]+EPSB); d_beff3[i]=b3[i]-m3[i]*s; }
    if (i < 10*EMB*C1) {
        int c = i % C1; int ci = (i / C1) % EMB; int u = i / (C1*EMB);
        float s = g2[c]*rsqrtf(v2[c]+EPSB);
        int klo = u-3; if (klo < 0) klo = 0;
        int khi = u < 6 ? u : 6;
        float acc = 0.f;
        for (int k = klo; k <= khi; k++) acc += w2[(k*EMB+ci)*C1 + c];
        d_weff2[i] = acc * s * 0.25f;
    }
    if (i < 10*C2*C2) {
        int c = i % C2; int ci = (i / C2) % C2; int u = i / (C2*C2);
        float s = g3[c]*rsqrtf(v3[c]+EPSB);
        int klo = u-3; if (klo < 0) klo = 0;
        int khi = u < 6 ? u : 6;
        float acc = 0.f;
        for (int k = klo; k <= khi; k++) acc += w3[(k*C2+ci)*C2 + c];
        d_weff3[i] = acc * s * 0.25f;
    }
}

// ---------------- 2: prefix scan -> CSR row starts, dinv ----------------
__global__ void k_scan() {
    __shared__ int sa[NN], sb[NN];
    int t = threadIdx.x;                       // 1024 threads
    sa[t] = d_rowcnt[t]; sa[t+1024] = d_rowcnt[t+1024];
    __syncthreads();
    int* cur = sa; int* nxt = sb;
    for (int off = 1; off < NN; off <<= 1) {
        for (int j = t; j < NN; j += 1024) {
            int v = cur[j];
            if (j >= off) v += cur[j-off];
            nxt[j] = v;
        }
        __syncthreads();
        int* tmp = cur; cur = nxt; nxt = tmp;
    }
    for (int j = t; j < NN; j += 1024) {
        int excl = (j == 0) ? 0 : cur[j-1];
        d_rowstart[j] = excl;
        d_cursor[j]   = excl;
        d_dinv[j]     = rsqrtf((float)(d_rowcnt[j] + 1));
        if (j == NN-1) d_rowstart[NN] = cur[NN-1];
    }
}

// ---------------- 3: scatter edges into CSR ----------------
__global__ void k_scatter(const int* __restrict__ edge) {
    int e = blockIdx.x * blockDim.x + threadIdx.x;
    if (e < EE) {
        int dd = edge[EE + e];
        int pos = atomicAdd(&d_cursor[dd], 1);
        d_csrsrc[pos] = edge[e];
    }
}

// ---------------- 4: conv1 + bn1 + relu: (N,T) -> (N,T,32) ----------------
__global__ void k_conv1(const float* __restrict__ x, const float* __restrict__ w) {
    __shared__ float xs[TT];
    __shared__ float ws[7*C0];
    __shared__ float ss[C0], bs[C0];
    int n = blockIdx.x, tid = threadIdx.x;     // 256 threads
    if (tid < TT)   xs[tid] = x[n*TT + tid];
    if (tid < 7*C0) ws[tid] = w[tid];
    if (tid < C0) { ss[tid] = d_s1[tid]; bs[tid] = d_b1e[tid]; }
    __syncthreads();
    int c = tid & 31, t0 = tid >> 5;
    for (int t = t0; t < TT; t += 8) {
        float acc = 0.f;
        #pragma unroll
        for (int k = 0; k < 7; k++) {
            int ti = t + k - 3;
            if (ti >= 0 && ti < TT) acc += xs[ti] * ws[k*C0 + c];
        }
        acc = acc * ss[c] + bs[c];
        d_h1[(n*TT + t)*C0 + c] = fmaxf(acc, 0.f);
    }
}

// ---------------- 5/7: CSR aggregation  out[i] = sum_j norm_ij * in[j] ----------------
__global__ void k_agg1() {           // rows of 2048 floats (h1 -> a1)
    int node = blockIdx.x;
    int off  = threadIdx.x * 4;      // 256 threads * 4, plus +1024
    float di = d_dinv[node];
    float w  = di * di;
    const float* base = d_h1 + (size_t)node*2048 + off;
    float4 v0 = *(const float4*)base;
    float4 v1 = *(const float4*)(base + 1024);
    float4 a0 = make_float4(v0.x*w, v0.y*w, v0.z*w, v0.w*w);
    float4 a1 = make_float4(v1.x*w, v1.y*w, v1.z*w, v1.w*w);
    int e0 = d_rowstart[node], e1 = d_rowstart[node+1];
    for (int e = e0; e < e1; e++) {
        int s = d_csrsrc[e];
        float ww = di * d_dinv[s];
        const float* sb = d_h1 + (size_t)s*2048 + off;
        float4 u0 = *(const float4*)sb;
        float4 u1 = *(const float4*)(sb + 1024);
        a0.x += ww*u0.x; a0.y += ww*u0.y; a0.z += ww*u0.z; a0.w += ww*u0.w;
        a1.x += ww*u1.x; a1.y += ww*u1.y; a1.z += ww*u1.z; a1.w += ww*u1.w;
    }
    float* ob = d_a1 + (size_t)node*2048 + off;
    *(float4*)ob = a0;
    *(float4*)(ob + 1024) = a1;
}

__global__ void k_agg2() {           // rows of 8192 floats (h2 -> a2), grid.y = 4 chunks
    int node = blockIdx.x;
    int off  = blockIdx.y*2048 + threadIdx.x*4;
    float di = d_dinv[node];
    float w  = di * di;
    const float* base = d_h2 + (size_t)node*8192 + off;
    float4 v0 = *(const float4*)base;
    float4 v1 = *(const float4*)(base + 1024);
    float4 a0 = make_float4(v0.x*w, v0.y*w, v0.z*w, v0.w*w);
    float4 a1 = make_float4(v1.x*w, v1.y*w, v1.z*w, v1.w*w);
    int e0 = d_rowstart[node], e1 = d_rowstart[node+1];
    for (int e = e0; e < e1; e++) {
        int s = d_csrsrc[e];
        float ww = di * d_dinv[s];
        const float* sb = d_h2 + (size_t)s*8192 + off;
        float4 u0 = *(const float4*)sb;
        float4 u1 = *(const float4*)(sb + 1024);
        a0.x += ww*u0.x; a0.y += ww*u0.y; a0.z += ww*u0.z; a0.w += ww*u0.w;
        a1.x += ww*u1.x; a1.y += ww*u1.y; a1.z += ww*u1.z; a1.w += ww*u1.w;
    }
    float* ob = d_a2 + (size_t)node*8192 + off;
    *(float4*)ob = a0;
    *(float4*)(ob + 1024) = a1;
}

// ---------------- 6: gcn1 matmul via tf32 mma: (131072,32)@(32,128)+bias+relu ----------
__global__ void __launch_bounds__(256) k_mm1_tc(const float* __restrict__ W,
                                               const float* __restrict__ bias) {
    __shared__ float As[128*36];
    __shared__ float Bs[32*132];
    int tid = threadIdx.x;
    int wid = tid >> 5, lane = tid & 31;
    int g = lane >> 2, tg = lane & 3;
    int rowbase = blockIdx.x * 128;
    int mrow = wid * 16;

    float acc[16][4];
    #pragma unroll
    for (int nt = 0; nt < 16; nt++) {
        int c = nt*8 + 2*tg;
        float b0 = bias[c], b1 = bias[c+1];
        acc[nt][0] = b0; acc[nt][1] = b1; acc[nt][2] = b0; acc[nt][3] = b1;
    }

    // load A: 128 rows x 32 k
    #pragma unroll
    for (int i = tid; i < 1024; i += 256) {
        int r = i >> 3, k4 = (i & 7) * 4;
        float4 v = to_tf32_4(*(const float4*)&d_a1[(size_t)(rowbase + r)*C0 + k4]);
        *(float4*)&As[r*36 + k4] = v;
    }
    // load B: 32 k x 128 n
    #pragma unroll
    for (int i = tid; i < 1024; i += 256) {
        int k = i >> 5, n4 = (i & 31) * 4;
        float4 v = to_tf32_4(*(const float4*)&W[(size_t)k*EMB + n4]);
        *(float4*)&Bs[k*132 + n4] = v;
    }
    __syncthreads();
    #pragma unroll
    for (int ks = 0; ks < 4; ks++) {
        int kb = ks * 8;
        uint32_t a0 = __float_as_uint(As[(mrow+g  )*36 + kb + tg]);
        uint32_t a1 = __float_as_uint(As[(mrow+g+8)*36 + kb + tg]);
        uint32_t a2 = __float_as_uint(As[(mrow+g  )*36 + kb + tg + 4]);
        uint32_t a3 = __float_as_uint(As[(mrow+g+8)*36 + kb + tg + 4]);
        #pragma unroll
        for (int nt = 0; nt < 16; nt++) {
            uint32_t b0 = __float_as_uint(Bs[(kb+tg  )*132 + nt*8 + g]);
            uint32_t b1 = __float_as_uint(Bs[(kb+tg+4)*132 + nt*8 + g]);
            asm volatile(
                "mma.sync.aligned.m16n8k8.row.col.f32.tf32.tf32.f32 "
                "{%0,%1,%2,%3}, {%4,%5,%6,%7}, {%8,%9}, {%0,%1,%2,%3};"
                : "+f"(acc[nt][0]), "+f"(acc[nt][1]), "+f"(acc[nt][2]), "+f"(acc[nt][3])
                : "r"(a0), "r"(a1), "r"(a2), "r"(a3), "r"(b0), "r"(b1));
        }
    }

    int row0 = rowbase + mrow + g;
    int row1 = row0 + 8;
    #pragma unroll
    for (int nt = 0; nt < 16; nt++) {
        int c = nt*8 + 2*tg;
        *(float2*)&d_h2[(size_t)row0*EMB + c] =
            make_float2(fmaxf(acc[nt][0], 0.f), fmaxf(acc[nt][1], 0.f));
        *(float2*)&d_h2[(size_t)row1*EMB + c] =
            make_float2(fmaxf(acc[nt][2], 0.f), fmaxf(acc[nt][3], 0.f));
    }
}

// ---------------- 8: gcn2 matmul via tf32 mma.sync: (131072,128)@(128,128)+bias+relu ----
__global__ void __launch_bounds__(256) k_mm2_tc(const float* __restrict__ W,
                                               const float* __restrict__ bias) {
    __shared__ float As[128*36];   // padded ld=36 -> conflict-free frag loads
    __shared__ float Bs[32*132];   // padded ld=132
    int tid = threadIdx.x;
    int wid = tid >> 5, lane = tid & 31;
    int g = lane >> 2, tg = lane & 3;
    int rowbase = blockIdx.x * 128;
    int mrow = wid * 16;

    float acc[16][4];
    #pragma unroll
    for (int nt = 0; nt < 16; nt++) {
        int c = nt*8 + 2*tg;
        float b0 = bias[c], b1 = bias[c+1];
        acc[nt][0] = b0; acc[nt][1] = b1; acc[nt][2] = b0; acc[nt][3] = b1;
    }

    for (int kc = 0; kc < 4; kc++) {
        #pragma unroll
        for (int i = tid; i < 1024; i += 256) {
            int r = i >> 3, k4 = (i & 7) * 4;
            float4 v = to_tf32_4(*(const float4*)&d_a2[(size_t)(rowbase + r)*EMB + kc*32 + k4]);
            *(float4*)&As[r*36 + k4] = v;
        }
        #pragma unroll
        for (int i = tid; i < 1024; i += 256) {
            int k = i >> 5, n4 = (i & 31) * 4;
            float4 v = to_tf32_4(*(const float4*)&W[(size_t)(kc*32 + k)*EMB + n4]);
            *(float4*)&Bs[k*132 + n4] = v;
        }
        __syncthreads();
        #pragma unroll
        for (int ks = 0; ks < 4; ks++) {
            int kb = ks * 8;
            uint32_t a0 = __float_as_uint(As[(mrow+g  )*36 + kb + tg]);
            uint32_t a1 = __float_as_uint(As[(mrow+g+8)*36 + kb + tg]);
            uint32_t a2 = __float_as_uint(As[(mrow+g  )*36 + kb + tg + 4]);
            uint32_t a3 = __float_as_uint(As[(mrow+g+8)*36 + kb + tg + 4]);
            #pragma unroll
            for (int nt = 0; nt < 16; nt++) {
                uint32_t b0 = __float_as_uint(Bs[(kb+tg  )*132 + nt*8 + g]);
                uint32_t b1 = __float_as_uint(Bs[(kb+tg+4)*132 + nt*8 + g]);
                asm volatile(
                    "mma.sync.aligned.m16n8k8.row.col.f32.tf32.tf32.f32 "
                    "{%0,%1,%2,%3}, {%4,%5,%6,%7}, {%8,%9}, {%0,%1,%2,%3};"
                    : "+f"(acc[nt][0]), "+f"(acc[nt][1]), "+f"(acc[nt][2]), "+f"(acc[nt][3])
                    : "r"(a0), "r"(a1), "r"(a2), "r"(a3), "r"(b0), "r"(b1));
            }
        }
        __syncthreads();
    }

    int row0 = rowbase + mrow + g;
    int row1 = row0 + 8;
    #pragma unroll
    for (int nt = 0; nt < 16; nt++) {
        int c = nt*8 + 2*tg;
        *(float2*)&d_h2[(size_t)row0*EMB + c] =
            make_float2(fmaxf(acc[nt][0], 0.f), fmaxf(acc[nt][1], 0.f));
        *(float2*)&d_h2[(size_t)row1*EMB + c] =
            make_float2(fmaxf(acc[nt][2], 0.f), fmaxf(acc[nt][3], 0.f));
    }
}

// ---------------- 9: conv2+bn2+avgpool+relu as implicit-im2col tf32 GEMM ----------------
// M = (node,p) pairs: 4 nodes/block -> 56 rows (padded to 64); N = 64; K = 1280 (u,ci).
// K chunked as (u, ci-half): 20 chunks of 64.
__global__ void __launch_bounds__(256) k_conv2_tc() {
    __shared__ float As[64*68];    // 17.4KB
    __shared__ float Bs[64*68];    // 17.4KB
    int tid = threadIdx.x;
    int wid = tid >> 5, lane = tid & 31;
    int g = lane >> 2, tg = lane & 3;
    int n0 = blockIdx.x * 4;
    int mt = wid >> 1;                 // 0..3, 16 rows each
    int nbase = (wid & 1) * 32;        // two warps split the 64 N-cols

    float acc[4][4];
    #pragma unroll
    for (int nt = 0; nt < 4; nt++) {
        int c = nbase + nt*8 + 2*tg;
        float b0 = d_beff2[c], b1 = d_beff2[c+1];
        acc[nt][0] = b0; acc[nt][1] = b1; acc[nt][2] = b0; acc[nt][3] = b1;
    }

    for (int u = 0; u < 10; u++) {
        for (int h = 0; h < 2; h++) {
            // A: 64 rows x 64 k (row = nl*14+p, k = ci = h*64 + kk)
            #pragma unroll
            for (int i = tid; i < 1024; i += 256) {
                int r = i >> 4, kk4 = (i & 15) * 4;
                float4 v = make_float4(0.f, 0.f, 0.f, 0.f);
                if (r < 56) {
                    int nl = r / 14, p = r - nl*14;
                    v = to_tf32_4(*(const float4*)
                        &d_h2[(size_t)((n0+nl)*TT + 4*p + u)*EMB + h*64 + kk4]);
                }
                *(float4*)&As[r*68 + kk4] = v;
            }
            // B: 64 ci x 64 c
            #pragma unroll
            for (int i = tid; i < 1024; i += 256) {
                int ci = i >> 4, c4 = (i & 15) * 4;
                float4 v = to_tf32_4(*(const float4*)
                    &d_weff2[(size_t)(u*EMB + h*64 + ci)*C1 + c4]);
                *(float4*)&Bs[ci*68 + c4] = v;
            }
            __syncthreads();
            #pragma unroll
            for (int ks = 0; ks < 8; ks++) {
                int kb = ks * 8;
                uint32_t a0 = __float_as_uint(As[(mt*16+g  )*68 + kb + tg]);
                uint32_t a1 = __float_as_uint(As[(mt*16+g+8)*68 + kb + tg]);
                uint32_t a2 = __float_as_uint(As[(mt*16+g  )*68 + kb + tg + 4]);
                uint32_t a3 = __float_as_uint(As[(mt*16+g+8)*68 + kb + tg + 4]);
                #pragma unroll
                for (int nt = 0; nt < 4; nt++) {
                    uint32_t b0 = __float_as_uint(Bs[(kb+tg  )*68 + nbase + nt*8 + g]);
                    uint32_t b1 = __float_as_uint(Bs[(kb+tg+4)*68 + nbase + nt*8 + g]);
                    asm volatile(
                        "mma.sync.aligned.m16n8k8.row.col.f32.tf32.tf32.f32 "
                        "{%0,%1,%2,%3}, {%4,%5,%6,%7}, {%8,%9}, {%0,%1,%2,%3};"
                        : "+f"(acc[nt][0]), "+f"(acc[nt][1]), "+f"(acc[nt][2]), "+f"(acc[nt][3])
                        : "r"(a0), "r"(a1), "r"(a2), "r"(a3), "r"(b0), "r"(b1));
                }
            }
            __syncthreads();
        }
    }

    int r0 = mt*16 + g;           // < 56 always
    int r1 = r0 + 8;              // valid only when mt < 3
    #pragma unroll
    for (int nt = 0; nt < 4; nt++) {
        int c = nbase + nt*8 + 2*tg;
        *(float2*)&d_pool[(size_t)(n0*14 + r0)*C1 + c] =
            make_float2(fmaxf(acc[nt][0], 0.f), fmaxf(acc[nt][1], 0.f));
        if (r1 < 56)
            *(float2*)&d_pool[(size_t)(n0*14 + r1)*C1 + c] =
                make_float2(fmaxf(acc[nt][2], 0.f), fmaxf(acc[nt][3], 0.f));
    }
}

// ---------------- 10: graph sum pool (atomic) ----------------
__global__ void k_gpool(const int* __restrict__ batch) {
    int i = blockIdx.x * blockDim.x + threadIdx.x;
    if (i < NN*14*C1) {
        int n = i / (14*C1);
        int rem = i - n*14*C1;
        atomicAdd(&d_gp[batch[n]*14*C1 + rem], d_pool[i]);
    }
}

// ---------------- 11: conv3+bn3+pool+relu + dense + log_softmax ----------------
__global__ void k_final(const float* __restrict__ dw, const float* __restrict__ db,
                        float* __restrict__ out) {
    __shared__ float gin[14*C1];
    __shared__ float flat[128];
    __shared__ float lg[4];
    int b = blockIdx.x, tid = threadIdx.x;     // 128 threads
    float inv = 1.f / d_counts[b];
    for (int i = tid; i < 14*C1; i += 128) gin[i] = d_gp[b*14*C1 + i] * inv;
    __syncthreads();
    int p = tid >> 6, c = tid & 63;
    float acc = d_beff3[c];
    for (int u = 0; u < 10; u++)
        for (int ci = 0; ci < C2; ci++)
            acc += gin[(4*p + u)*C2 + ci] * d_weff3[(u*C2 + ci)*C2 + c];
    flat[p*64 + c] = fmaxf(acc, 0.f);
    __syncthreads();
    if (tid < 4) {
        float a = db[tid];
        for (int i = 0; i < 128; i++) a += flat[i] * dw[i*4 + tid];
        lg[tid] = a;
    }
    __syncthreads();
    if (tid == 0) {
        float m = fmaxf(fmaxf(lg[0], lg[1]), fmaxf(lg[2], lg[3]));
        float se = expf(lg[0]-m) + expf(lg[1]-m) + expf(lg[2]-m) + expf(lg[3]-m);
        float lse = logf(se) + m;
        for (int j = 0; j < 4; j++) out[b*4 + j] = lg[j] - lse;
    }
}

// ---------------- launcher ----------------
extern "C" void kernel_launch(void* const* d_in, const int* in_sizes, int n_in,
                              void* d_out, int out_size) {
    const float* x       = (const float*)d_in[0];
    const int*   edge    = (const int*)d_in[1];
    const int*   batch   = (const int*)d_in[2];
    const float* conv1_w = (const float*)d_in[3];
    const float* bn1_g   = (const float*)d_in[4];
    const float* bn1_b   = (const float*)d_in[5];
    const float* bn1_m   = (const float*)d_in[6];
    const float* bn1_v   = (const float*)d_in[7];
    const float* gcn1_w  = (const float*)d_in[8];
    const float* gcn1_b  = (const float*)d_in[9];
    const float* gcn2_w  = (const float*)d_in[10];
    const float* gcn2_b  = (const float*)d_in[11];
    const float* conv2_w = (const float*)d_in[12];
    const float* bn2_g   = (const float*)d_in[13];
    const float* bn2_b   = (const float*)d_in[14];
    const float* bn2_m   = (const float*)d_in[15];
    const float* bn2_v   = (const float*)d_in[16];
    const float* conv3_w = (const float*)d_in[17];
    const float* bn3_g   = (const float*)d_in[18];
    const float* bn3_b   = (const float*)d_in[19];
    const float* bn3_m   = (const float*)d_in[20];
    const float* bn3_v   = (const float*)d_in[21];
    const float* dense_w = (const float*)d_in[22];
    const float* dense_b = (const float*)d_in[23];
    float* out = (float*)d_out;

    k_zero<<<224, 256>>>();
    k_prep<<<320, 256>>>(edge, batch, bn1_g, bn1_b, bn1_m, bn1_v,
                         conv2_w, bn2_g, bn2_b, bn2_m, bn2_v,
                         conv3_w, bn3_g, bn3_b, bn3_m, bn3_v);
    k_scan<<<1, 1024>>>();
    k_scatter<<<64, 256>>>(edge);
    k_conv1<<<NN, 256>>>(x, conv1_w);
    k_agg1<<<NN, 256>>>();
    k_mm1_tc<<<1024, 256>>>(gcn1_w, gcn1_b);
    k_agg2<<<dim3(NN, 4), 256>>>();
    k_mm2_tc<<<1024, 256>>>(gcn2_w, gcn2_b);
    k_conv2_tc<<<512, 256>>>();
    k_gpool<<<7168, 256>>>(batch);
    k_final<<<BB, 128>>>(dense_w, dense_b, out);
}

// round 4
// speedup vs baseline: 4.2363x; 1.4588x over previous
#include <cuda_runtime.h>
#include <cuda_bf16.h>
#include <math.h>
#include <stdint.h>

#define NN  2048
#define TT  64
#define EE  16384
#define BB  64
#define C0  32
#define EMB 128
#define C1  64
#define C2  64
#define EPSB 1e-5f

// ---------------- scratch (device globals) ----------------
__device__ __nv_bfloat16 d_h1b[NN*TT*C0];    // conv1 out (8MB)
__device__ __nv_bfloat16 d_a1b[NN*TT*C0];    // agg1 out  (8MB)
__device__ __nv_bfloat16 d_h2b[NN*TT*EMB];   // gcn1/gcn2 out (32MB)
__device__ __nv_bfloat16 d_a2b[NN*TT*EMB];   // agg2 out  (32MB)
__device__ float d_pool[NN*14*C1];
__device__ float d_gp[BB*14*C1];
__device__ float d_counts[BB];
__device__ int   d_rowstart[NN+1];
__device__ int   d_csrsrc[EE];
__device__ float d_dinv[NN];
__device__ __nv_bfloat16 d_w1tb[EMB*C0];       // gcn1 W transposed [n][k] bf16
__device__ __nv_bfloat16 d_w2tb[EMB*EMB];      // gcn2 W transposed [n][k] bf16
__device__ __nv_bfloat16 d_weff2tb[C1*1280];   // conv2 eff W transposed [c][u*128+ci] bf16
__device__ float d_beff2[C1];
__device__ float d_weff3[10*C2*C2];
__device__ float d_beff3[C2];
__device__ float d_s1[C0];
__device__ float d_b1e[C0];

// ---------------- 0: zero accumulators ----------------
__global__ void k_zero() {
    int i = blockIdx.x * blockDim.x + threadIdx.x;
    if (i < BB*14*C1) d_gp[i] = 0.f;
    if (i < BB)       d_counts[i] = 0.f;
}

// ---------------- 1: prep (batch counts, folded/transposed weights) ----------------
__global__ void k_prep(const int* __restrict__ batch,
                       const float* __restrict__ g1, const float* __restrict__ b1,
                       const float* __restrict__ m1, const float* __restrict__ v1,
                       const float* __restrict__ w1, const float* __restrict__ wg2,
                       const float* __restrict__ w2, const float* __restrict__ g2,
                       const float* __restrict__ b2, const float* __restrict__ m2,
                       const float* __restrict__ v2,
                       const float* __restrict__ w3, const float* __restrict__ g3,
                       const float* __restrict__ b3, const float* __restrict__ m3,
                       const float* __restrict__ v3) {
    int i = blockIdx.x * blockDim.x + threadIdx.x;
    if (i < NN) atomicAdd(&d_counts[batch[i]], 1.0f);
    if (i < C0) { float s = g1[i]*rsqrtf(v1[i]+EPSB); d_s1[i]=s; d_b1e[i]=b1[i]-m1[i]*s; }
    if (i < C1) { float s = g2[i]*rsqrtf(v2[i]+EPSB); d_beff2[i]=b2[i]-m2[i]*s; }
    if (i < C2) { float s = g3[i]*rsqrtf(v3[i]+EPSB); d_beff3[i]=b3[i]-m3[i]*s; }
    // gcn1 W: [32][128] -> [n][k] bf16
    if (i < EMB*C0) {
        int n = i >> 5, k = i & 31;
        d_w1tb[i] = __float2bfloat16(w1[k*EMB + n]);
    }
    // gcn2 W: [128][128] -> [n][k] bf16
    if (i < EMB*EMB) {
        int n = i >> 7, k = i & 127;
        d_w2tb[i] = __float2bfloat16(wg2[k*EMB + n]);
    }
    // conv2 eff W: fold pool+bn, transpose to [c][u*128+ci] bf16
    if (i < C1*1280) {
        int c = i / 1280, kk = i - c*1280;
        int u = kk >> 7, ci = kk & 127;
        float s = g2[c]*rsqrtf(v2[c]+EPSB);
        int klo = u-3; if (klo < 0) klo = 0;
        int khi = u < 6 ? u : 6;
        float acc = 0.f;
        for (int k = klo; k <= khi; k++) acc += w2[(k*EMB+ci)*C1 + c];
        d_weff2tb[i] = __float2bfloat16(acc * s * 0.25f);
    }
    // conv3 eff W (fp32, tiny)
    if (i < 10*C2*C2) {
        int c = i % C2; int ci = (i / C2) % C2; int u = i / (C2*C2);
        float s = g3[c]*rsqrtf(v3[c]+EPSB);
        int klo = u-3; if (klo < 0) klo = 0;
        int khi = u < 6 ? u : 6;
        float acc = 0.f;
        for (int k = klo; k <= khi; k++) acc += w3[(k*C2+ci)*C2 + c];
        d_weff3[i] = acc * s * 0.25f;
    }
}

// ---------------- 2: single-block graph prep: degree, scan, dinv, CSR scatter ---------
__global__ void __launch_bounds__(1024) k_graph(const int* __restrict__ edge) {
    __shared__ int cnt[NN];
    __shared__ int s2[NN];
    __shared__ int scur[NN];
    int t = threadIdx.x;
    cnt[t] = 0; cnt[t+1024] = 0;
    __syncthreads();
    for (int e = t; e < EE; e += 1024) atomicAdd(&cnt[edge[EE + e]], 1);
    __syncthreads();
    // dinv before scan destroys nothing (scan ping-pongs cnt<->s2)
    d_dinv[t]      = rsqrtf((float)(cnt[t] + 1));
    d_dinv[t+1024] = rsqrtf((float)(cnt[t+1024] + 1));
    int* cur = cnt; int* nxt = s2;
    for (int off = 1; off < NN; off <<= 1) {
        for (int j = t; j < NN; j += 1024) {
            int v = cur[j];
            if (j >= off) v += cur[j-off];
            nxt[j] = v;
        }
        __syncthreads();
        int* tmp = cur; cur = nxt; nxt = tmp;
    }
    for (int j = t; j < NN; j += 1024) {
        int excl = (j == 0) ? 0 : cur[j-1];
        d_rowstart[j] = excl;
        scur[j] = excl;
        if (j == NN-1) d_rowstart[NN] = cur[NN-1];
    }
    __syncthreads();
    for (int e = t; e < EE; e += 1024) {
        int dd = edge[EE + e];
        int pos = atomicAdd(&scur[dd], 1);
        d_csrsrc[pos] = edge[e];
    }
}

// ---------------- 3: conv1 + bn1 + relu -> bf16: (N,T) -> (N,T,32) ----------------
__global__ void k_conv1(const float* __restrict__ x, const float* __restrict__ w) {
    __shared__ float xs[TT];
    __shared__ float ws[7*C0];
    __shared__ float ss[C0], bs[C0];
    int n = blockIdx.x, tid = threadIdx.x;     // 256 threads
    if (tid < TT)   xs[tid] = x[n*TT + tid];
    if (tid < 7*C0) ws[tid] = w[tid];
    if (tid < C0) { ss[tid] = d_s1[tid]; bs[tid] = d_b1e[tid]; }
    __syncthreads();
    int c = tid & 31, t0 = tid >> 5;
    for (int t = t0; t < TT; t += 8) {
        float acc = 0.f;
        #pragma unroll
        for (int k = 0; k < 7; k++) {
            int ti = t + k - 3;
            if (ti >= 0 && ti < TT) acc += xs[ti] * ws[k*C0 + c];
        }
        acc = acc * ss[c] + bs[c];
        d_h1b[(n*TT + t)*C0 + c] = __float2bfloat16(fmaxf(acc, 0.f));
    }
}

// ---------------- bf16 gather-aggregate helpers ----------------
__device__ __forceinline__ void acc_row8(float* a, const __nv_bfloat16* p, float w) {
    uint4 v = *(const uint4*)p;
    const __nv_bfloat162* b = (const __nv_bfloat162*)&v;
    #pragma unroll
    for (int j = 0; j < 4; j++) {
        float2 f = __bfloat1622float2(b[j]);
        a[2*j]   += w * f.x;
        a[2*j+1] += w * f.y;
    }
}
__device__ __forceinline__ void store_row8(__nv_bfloat16* p, const float* a) {
    uint4 o;
    __nv_bfloat162* b = (__nv_bfloat162*)&o;
    #pragma unroll
    for (int j = 0; j < 4; j++) b[j] = __floats2bfloat162_rn(a[2*j], a[2*j+1]);
    *(uint4*)p = o;
}

// ---------------- 4: agg1 (bf16): rows of 2048 ----------------
__global__ void k_agg1b() {
    int node = blockIdx.x;
    int off  = threadIdx.x * 8;      // 256 threads * 8
    float di = d_dinv[node];
    float a[8] = {0,0,0,0,0,0,0,0};
    acc_row8(a, d_h1b + (size_t)node*2048 + off, di*di);
    int e0 = d_rowstart[node], e1 = d_rowstart[node+1];
    for (int e = e0; e < e1; e++) {
        int s = d_csrsrc[e];
        acc_row8(a, d_h1b + (size_t)s*2048 + off, di * d_dinv[s]);
    }
    store_row8(d_a1b + (size_t)node*2048 + off, a);
}

// ---------------- 6: agg2 (bf16): rows of 8192, grid.y=4 ----------------
__global__ void k_agg2b() {
    int node = blockIdx.x;
    int off  = blockIdx.y*2048 + threadIdx.x * 8;
    float di = d_dinv[node];
    float a[8] = {0,0,0,0,0,0,0,0};
    acc_row8(a, d_h2b + (size_t)node*8192 + off, di*di);
    int e0 = d_rowstart[node], e1 = d_rowstart[node+1];
    for (int e = e0; e < e1; e++) {
        int s = d_csrsrc[e];
        acc_row8(a, d_h2b + (size_t)s*8192 + off, di * d_dinv[s]);
    }
    store_row8(d_a2b + (size_t)node*8192 + off, a);
}

// ---------------- bf16 mma macro ----------------
#define MMA_BF16(acc, A0, A1, A2, A3, B0, B1)                                   \
    asm volatile(                                                               \
        "mma.sync.aligned.m16n8k16.row.col.f32.bf16.bf16.f32 "                  \
        "{%0,%1,%2,%3}, {%4,%5,%6,%7}, {%8,%9}, {%0,%1,%2,%3};"                 \
        : "+f"(acc[0]), "+f"(acc[1]), "+f"(acc[2]), "+f"(acc[3])                \
        : "r"(A0), "r"(A1), "r"(A2), "r"(A3), "r"(B0), "r"(B1))

// ---------------- 5: gcn1 matmul bf16 mma: (131072,32)@(32,128)+bias+relu -> bf16 -----
__global__ void __launch_bounds__(256) k_mm1b(const float* __restrict__ bias) {
    __shared__ __nv_bfloat16 As[128*40];   // lda=40 conflict-free
    __shared__ __nv_bfloat16 Bs[128*40];
    int tid = threadIdx.x;
    int wid = tid >> 5, lane = tid & 31;
    int g = lane >> 2, tg = lane & 3;
    int rowbase = blockIdx.x * 128;
    int mrow = wid * 16;

    float acc[16][4];
    #pragma unroll
    for (int nt = 0; nt < 16; nt++) {
        int c = nt*8 + 2*tg;
        float b0 = bias[c], b1 = bias[c+1];
        acc[nt][0] = b0; acc[nt][1] = b1; acc[nt][2] = b0; acc[nt][3] = b1;
    }
    // stage A: 128 rows x 32 k
    #pragma unroll
    for (int i = tid; i < 512; i += 256) {
        int r = i >> 2, k8 = (i & 3) * 8;
        uint4 v = *(const uint4*)&d_a1b[(size_t)(rowbase + r)*C0 + k8];
        *(uint4*)&As[r*40 + k8] = v;
    }
    // stage B: 128 n x 32 k
    #pragma unroll
    for (int i = tid; i < 512; i += 256) {
        int r = i >> 2, k8 = (i & 3) * 8;
        uint4 v = *(const uint4*)&d_w1tb[r*C0 + k8];
        *(uint4*)&Bs[r*40 + k8] = v;
    }
    __syncthreads();
    #pragma unroll
    for (int ks = 0; ks < 32; ks += 16) {
        uint32_t a0 = *(const uint32_t*)&As[(mrow+g  )*40 + ks + 2*tg];
        uint32_t a1 = *(const uint32_t*)&As[(mrow+g+8)*40 + ks + 2*tg];
        uint32_t a2 = *(const uint32_t*)&As[(mrow+g  )*40 + ks + 2*tg + 8];
        uint32_t a3 = *(const uint32_t*)&As[(mrow+g+8)*40 + ks + 2*tg + 8];
        #pragma unroll
        for (int nt = 0; nt < 16; nt++) {
            uint32_t b0 = *(const uint32_t*)&Bs[(nt*8+g)*40 + ks + 2*tg];
            uint32_t b1 = *(const uint32_t*)&Bs[(nt*8+g)*40 + ks + 2*tg + 8];
            MMA_BF16(acc[nt], a0, a1, a2, a3, b0, b1);
        }
    }
    int row0 = rowbase + mrow + g;
    int row1 = row0 + 8;
    #pragma unroll
    for (int nt = 0; nt < 16; nt++) {
        int c = nt*8 + 2*tg;
        *(__nv_bfloat162*)&d_h2b[(size_t)row0*EMB + c] =
            __floats2bfloat162_rn(fmaxf(acc[nt][0], 0.f), fmaxf(acc[nt][1], 0.f));
        *(__nv_bfloat162*)&d_h2b[(size_t)row1*EMB + c] =
            __floats2bfloat162_rn(fmaxf(acc[nt][2], 0.f), fmaxf(acc[nt][3], 0.f));
    }
}

// ---------------- 7: gcn2 matmul bf16 mma: (131072,128)@(128,128)+bias+relu -> bf16 ---
__global__ void __launch_bounds__(256) k_mm2b(const float* __restrict__ bias) {
    __shared__ __nv_bfloat16 As[128*40];
    __shared__ __nv_bfloat16 Bs[128*40];
    int tid = threadIdx.x;
    int wid = tid >> 5, lane = tid & 31;
    int g = lane >> 2, tg = lane & 3;
    int rowbase = blockIdx.x * 128;
    int mrow = wid * 16;

    float acc[16][4];
    #pragma unroll
    for (int nt = 0; nt < 16; nt++) {
        int c = nt*8 + 2*tg;
        float b0 = bias[c], b1 = bias[c+1];
        acc[nt][0] = b0; acc[nt][1] = b1; acc[nt][2] = b0; acc[nt][3] = b1;
    }
    for (int kc = 0; kc < 4; kc++) {
        #pragma unroll
        for (int i = tid; i < 512; i += 256) {
            int r = i >> 2, k8 = (i & 3) * 8;
            uint4 v = *(const uint4*)&d_a2b[(size_t)(rowbase + r)*EMB + kc*32 + k8];
            *(uint4*)&As[r*40 + k8] = v;
        }
        #pragma unroll
        for (int i = tid; i < 512; i += 256) {
            int r = i >> 2, k8 = (i & 3) * 8;
            uint4 v = *(const uint4*)&d_w2tb[r*EMB + kc*32 + k8];
            *(uint4*)&Bs[r*40 + k8] = v;
        }
        __syncthreads();
        #pragma unroll
        for (int ks = 0; ks < 32; ks += 16) {
            uint32_t a0 = *(const uint32_t*)&As[(mrow+g  )*40 + ks + 2*tg];
            uint32_t a1 = *(const uint32_t*)&As[(mrow+g+8)*40 + ks + 2*tg];
            uint32_t a2 = *(const uint32_t*)&As[(mrow+g  )*40 + ks + 2*tg + 8];
            uint32_t a3 = *(const uint32_t*)&As[(mrow+g+8)*40 + ks + 2*tg + 8];
            #pragma unroll
            for (int nt = 0; nt < 16; nt++) {
                uint32_t b0 = *(const uint32_t*)&Bs[(nt*8+g)*40 + ks + 2*tg];
                uint32_t b1 = *(const uint32_t*)&Bs[(nt*8+g)*40 + ks + 2*tg + 8];
                MMA_BF16(acc[nt], a0, a1, a2, a3, b0, b1);
            }
        }
        __syncthreads();
    }
    int row0 = rowbase + mrow + g;
    int row1 = row0 + 8;
    #pragma unroll
    for (int nt = 0; nt < 16; nt++) {
        int c = nt*8 + 2*tg;
        *(__nv_bfloat162*)&d_h2b[(size_t)row0*EMB + c] =
            __floats2bfloat162_rn(fmaxf(acc[nt][0], 0.f), fmaxf(acc[nt][1], 0.f));
        *(__nv_bfloat162*)&d_h2b[(size_t)row1*EMB + c] =
            __floats2bfloat162_rn(fmaxf(acc[nt][2], 0.f), fmaxf(acc[nt][3], 0.f));
    }
}

// ---------------- 8: conv2+bn2+avgpool+relu as implicit-im2col bf16 GEMM --------------
// 4 nodes/block -> M=56 (pad 64); N=64; K = 20 chunks of 64 (u, ci-half).
__global__ void __launch_bounds__(256) k_conv2b() {
    __shared__ __nv_bfloat16 As[64*72];   // lda=72 conflict-free
    __shared__ __nv_bfloat16 Bs[64*72];
    int tid = threadIdx.x;
    int wid = tid >> 5, lane = tid & 31;
    int g = lane >> 2, tg = lane & 3;
    int n0 = blockIdx.x * 4;
    int mt = wid >> 1;
    int nbase = (wid & 1) * 32;

    float acc[4][4];
    #pragma unroll
    for (int nt = 0; nt < 4; nt++) {
        int c = nbase + nt*8 + 2*tg;
        float b0 = d_beff2[c], b1 = d_beff2[c+1];
        acc[nt][0] = b0; acc[nt][1] = b1; acc[nt][2] = b0; acc[nt][3] = b1;
    }
    for (int u = 0; u < 10; u++) {
        for (int h = 0; h < 2; h++) {
            // A: 64 rows x 64 k
            #pragma unroll
            for (int i = tid; i < 512; i += 256) {
                int r = i >> 3, k8 = (i & 7) * 8;
                uint4 v = make_uint4(0u, 0u, 0u, 0u);
                if (r < 56) {
                    int nl = r / 14, p = r - nl*14;
                    v = *(const uint4*)
                        &d_h2b[(size_t)((n0+nl)*TT + 4*p + u)*EMB + h*64 + k8];
                }
                *(uint4*)&As[r*72 + k8] = v;
            }
            // B: 64 c x 64 k from d_weff2tb[c][u*128 + h*64 + k]
            #pragma unroll
            for (int i = tid; i < 512; i += 256) {
                int c = i >> 3, k8 = (i & 7) * 8;
                uint4 v = *(const uint4*)&d_weff2tb[(size_t)c*1280 + u*128 + h*64 + k8];
                *(uint4*)&Bs[c*72 + k8] = v;
            }
            __syncthreads();
            #pragma unroll
            for (int ks = 0; ks < 64; ks += 16) {
                uint32_t a0 = *(const uint32_t*)&As[(mt*16+g  )*72 + ks + 2*tg];
                uint32_t a1 = *(const uint32_t*)&As[(mt*16+g+8)*72 + ks + 2*tg];
                uint32_t a2 = *(const uint32_t*)&As[(mt*16+g  )*72 + ks + 2*tg + 8];
                uint32_t a3 = *(const uint32_t*)&As[(mt*16+g+8)*72 + ks + 2*tg + 8];
                #pragma unroll
                for (int nt = 0; nt < 4; nt++) {
                    uint32_t b0 = *(const uint32_t*)&Bs[(nbase+nt*8+g)*72 + ks + 2*tg];
                    uint32_t b1 = *(const uint32_t*)&Bs[(nbase+nt*8+g)*72 + ks + 2*tg + 8];
                    MMA_BF16(acc[nt], a0, a1, a2, a3, b0, b1);
                }
            }
            __syncthreads();
        }
    }
    int r0 = mt*16 + g;
    int r1 = r0 + 8;
    #pragma unroll
    for (int nt = 0; nt < 4; nt++) {
        int c = nbase + nt*8 + 2*tg;
        *(float2*)&d_pool[(size_t)(n0*14 + r0)*C1 + c] =
            make_float2(fmaxf(acc[nt][0], 0.f), fmaxf(acc[nt][1], 0.f));
        if (r1 < 56)
            *(float2*)&d_pool[(size_t)(n0*14 + r1)*C1 + c] =
                make_float2(fmaxf(acc[nt][2], 0.f), fmaxf(acc[nt][3], 0.f));
    }
}

// ---------------- 9: graph sum pool (atomic) ----------------
__global__ void k_gpool(const int* __restrict__ batch) {
    int i = blockIdx.x * blockDim.x + threadIdx.x;
    if (i < NN*14*C1) {
        int n = i / (14*C1);
        int rem = i - n*14*C1;
        atomicAdd(&d_gp[batch[n]*14*C1 + rem], d_pool[i]);
    }
}

// ---------------- 10: conv3+bn3+pool+relu + dense + log_softmax ----------------
__global__ void k_final(const float* __restrict__ dw, const float* __restrict__ db,
                        float* __restrict__ out) {
    __shared__ float gin[14*C1];
    __shared__ float flat[128];
    __shared__ float lg[4];
    int b = blockIdx.x, tid = threadIdx.x;     // 128 threads
    float inv = 1.f / d_counts[b];
    for (int i = tid; i < 14*C1; i += 128) gin[i] = d_gp[b*14*C1 + i] * inv;
    __syncthreads();
    int p = tid >> 6, c = tid & 63;
    float acc = d_beff3[c];
    for (int u = 0; u < 10; u++)
        for (int ci = 0; ci < C2; ci++)
            acc += gin[(4*p + u)*C2 + ci] * d_weff3[(u*C2 + ci)*C2 + c];
    flat[p*64 + c] = fmaxf(acc, 0.f);
    __syncthreads();
    if (tid < 4) {
        float a = db[tid];
        for (int i = 0; i < 128; i++) a += flat[i] * dw[i*4 + tid];
        lg[tid] = a;
    }
    __syncthreads();
    if (tid == 0) {
        float m = fmaxf(fmaxf(lg[0], lg[1]), fmaxf(lg[2], lg[3]));
        float se = expf(lg[0]-m) + expf(lg[1]-m) + expf(lg[2]-m) + expf(lg[3]-m);
        float lse = logf(se) + m;
        for (int j = 0; j < 4; j++) out[b*4 + j] = lg[j] - lse;
    }
}

// ---------------- launcher ----------------
extern "C" void kernel_launch(void* const* d_in, const int* in_sizes, int n_in,
                              void* d_out, int out_size) {
    const float* x       = (const float*)d_in[0];
    const int*   edge    = (const int*)d_in[1];
    const int*   batch   = (const int*)d_in[2];
    const float* conv1_w = (const float*)d_in[3];
    const float* bn1_g   = (const float*)d_in[4];
    const float* bn1_b   = (const float*)d_in[5];
    const float* bn1_m   = (const float*)d_in[6];
    const float* bn1_v   = (const float*)d_in[7];
    const float* gcn1_w  = (const float*)d_in[8];
    const float* gcn1_b  = (const float*)d_in[9];
    const float* gcn2_w  = (const float*)d_in[10];
    const float* gcn2_b  = (const float*)d_in[11];
    const float* conv2_w = (const float*)d_in[12];
    const float* bn2_g   = (const float*)d_in[13];
    const float* bn2_b   = (const float*)d_in[14];
    const float* bn2_m   = (const float*)d_in[15];
    const float* bn2_v   = (const float*)d_in[16];
    const float* conv3_w = (const float*)d_in[17];
    const float* bn3_g   = (const float*)d_in[18];
    const float* bn3_b   = (const float*)d_in[19];
    const float* bn3_m   = (const float*)d_in[20];
    const float* bn3_v   = (const float*)d_in[21];
    const float* dense_w = (const float*)d_in[22];
    const float* dense_b = (const float*)d_in[23];
    float* out = (float*)d_out;

    k_zero<<<224, 256>>>();
    k_prep<<<320, 256>>>(batch, bn1_g, bn1_b, bn1_m, bn1_v,
                         gcn1_w, gcn2_w,
                         conv2_w, bn2_g, bn2_b, bn2_m, bn2_v,
                         conv3_w, bn3_g, bn3_b, bn3_m, bn3_v);
    k_graph<<<1, 1024>>>(edge);
    k_conv1<<<NN, 256>>>(x, conv1_w);
    k_agg1b<<<NN, 256>>>();
    k_mm1b<<<1024, 256>>>(gcn1_b);
    k_agg2b<<<dim3(NN, 4), 256>>>();
    k_mm2b<<<1024, 256>>>(gcn2_b);
    k_conv2b<<<512, 256>>>();
    k_gpool<<<7168, 256>>>(batch);
    k_final<<<BB, 128>>>(dense_w, dense_b, out);
}

// round 6
// speedup vs baseline: 4.2764x; 1.0095x over previous
#include <cuda_runtime.h>
#include <cuda_bf16.h>
#include <math.h>
#include <stdint.h>

#define NN  2048
#define TT  64
#define EE  16384
#define BB  64
#define C0  32
#define EMB 128
#define C1  64
#define C2  64
#define EPSB 1e-5f

// ---------------- scratch (device globals) ----------------
__device__ __nv_bfloat16 d_h1b[NN*TT*C0];    // conv1 out (8MB)
__device__ __nv_bfloat16 d_a1b[NN*TT*C0];    // agg1 out  (8MB)
__device__ __nv_bfloat16 d_h2b[NN*TT*EMB];   // gcn1/gcn2 out (32MB)
__device__ __nv_bfloat16 d_a2b[NN*TT*EMB];   // agg2 out  (32MB)
__device__ float d_gp[BB*14*C1];
__device__ float d_counts[BB];
__device__ int   d_rowstart[NN+1];
__device__ int   d_csrsrc[EE];
__device__ float d_dinv[NN];
__device__ __nv_bfloat16 d_w1tb[EMB*C0];       // gcn1 W transposed [n][k] bf16
__device__ __nv_bfloat16 d_w2tb[EMB*EMB];      // gcn2 W transposed [n][k] bf16
__device__ __nv_bfloat16 d_weff2tb[C1*1280];   // conv2 eff W transposed [c][u*128+ci] bf16
__device__ float d_beff2[C1];
__device__ float d_weff3[10*C2*C2];
__device__ float d_beff3[C2];
__device__ float d_s1[C0];
__device__ float d_b1e[C0];

// ---------------- 1: single-block graph prep: zero, degree, scan, dinv, CSR ----------
__global__ void __launch_bounds__(1024) k_graph(const int* __restrict__ edge) {
    __shared__ int cnt[NN];
    __shared__ int s2[NN];
    __shared__ int scur[NN];
    int t = threadIdx.x;
    // zero global accumulators (runs before k_prep's count atomics)
    for (int i = t; i < BB*14*C1; i += 1024) d_gp[i] = 0.f;
    if (t < BB) d_counts[t] = 0.f;
    cnt[t] = 0; cnt[t+1024] = 0;
    __syncthreads();
    for (int e = t; e < EE; e += 1024) atomicAdd(&cnt[edge[EE + e]], 1);
    __syncthreads();
    d_dinv[t]      = rsqrtf((float)(cnt[t] + 1));
    d_dinv[t+1024] = rsqrtf((float)(cnt[t+1024] + 1));
    int* cur = cnt; int* nxt = s2;
    for (int off = 1; off < NN; off <<= 1) {
        for (int j = t; j < NN; j += 1024) {
            int v = cur[j];
            if (j >= off) v += cur[j-off];
            nxt[j] = v;
        }
        __syncthreads();
        int* tmp = cur; cur = nxt; nxt = tmp;
    }
    for (int j = t; j < NN; j += 1024) {
        int excl = (j == 0) ? 0 : cur[j-1];
        d_rowstart[j] = excl;
        scur[j] = excl;
        if (j == NN-1) d_rowstart[NN] = cur[NN-1];
    }
    __syncthreads();
    for (int e = t; e < EE; e += 1024) {
        int dd = edge[EE + e];
        int pos = atomicAdd(&scur[dd], 1);
        d_csrsrc[pos] = edge[e];
    }
}

// ---------------- 2: prep (batch counts, folded/transposed weights) ----------------
__global__ void k_prep(const int* __restrict__ batch,
                       const float* __restrict__ g1, const float* __restrict__ b1,
                       const float* __restrict__ m1, const float* __restrict__ v1,
                       const float* __restrict__ w1, const float* __restrict__ wg2,
                       const float* __restrict__ w2, const float* __restrict__ g2,
                       const float* __restrict__ b2, const float* __restrict__ m2,
                       const float* __restrict__ v2,
                       const float* __restrict__ w3, const float* __restrict__ g3,
                       const float* __restrict__ b3, const float* __restrict__ m3,
                       const float* __restrict__ v3) {
    int i = blockIdx.x * blockDim.x + threadIdx.x;
    if (i < NN) atomicAdd(&d_counts[batch[i]], 1.0f);
    if (i < C0) { float s = g1[i]*rsqrtf(v1[i]+EPSB); d_s1[i]=s; d_b1e[i]=b1[i]-m1[i]*s; }
    if (i < C1) { float s = g2[i]*rsqrtf(v2[i]+EPSB); d_beff2[i]=b2[i]-m2[i]*s; }
    if (i < C2) { float s = g3[i]*rsqrtf(v3[i]+EPSB); d_beff3[i]=b3[i]-m3[i]*s; }
    if (i < EMB*C0) {
        int n = i >> 5, k = i & 31;
        d_w1tb[i] = __float2bfloat16(w1[k*EMB + n]);
    }
    if (i < EMB*EMB) {
        int n = i >> 7, k = i & 127;
        d_w2tb[i] = __float2bfloat16(wg2[k*EMB + n]);
    }
    if (i < C1*1280) {
        int c = i / 1280, kk = i - c*1280;
        int u = kk >> 7, ci = kk & 127;
        float s = g2[c]*rsqrtf(v2[c]+EPSB);
        int klo = u-3; if (klo < 0) klo = 0;
        int khi = u < 6 ? u : 6;
        float acc = 0.f;
        for (int k = klo; k <= khi; k++) acc += w2[(k*EMB+ci)*C1 + c];
        d_weff2tb[i] = __float2bfloat16(acc * s * 0.25f);
    }
    if (i < 10*C2*C2) {
        int c = i % C2; int ci = (i / C2) % C2; int u = i / (C2*C2);
        float s = g3[c]*rsqrtf(v3[c]+EPSB);
        int klo = u-3; if (klo < 0) klo = 0;
        int khi = u < 6 ? u : 6;
        float acc = 0.f;
        for (int k = klo; k <= khi; k++) acc += w3[(k*C2+ci)*C2 + c];
        d_weff3[i] = acc * s * 0.25f;
    }
}

// ---------------- 3: conv1 + bn1 + relu -> bf16 (vectorized, no predicates) ----------
__global__ void __launch_bounds__(128) k_conv1(const float* __restrict__ x,
                                               const float* __restrict__ w) {
    __shared__ float xs[TT + 6];   // zero-padded halo
    __shared__ float ws[7*C0];
    __shared__ float ss[C0], bs[C0];
    int n = blockIdx.x, tid = threadIdx.x;     // 128 threads
    if (tid < TT) xs[tid + 3] = x[n*TT + tid];
    if (tid < 3)  { xs[tid] = 0.f; xs[TT + 3 + tid] = 0.f; }
    for (int i = tid; i < 7*C0; i += 128) ws[i] = w[i];   // FIX: stride loop (224 > 128)
    if (tid < C0) { ss[tid] = d_s1[tid]; bs[tid] = d_b1e[tid]; }
    __syncthreads();
    int t = tid >> 1, cb = (tid & 1) * 16;
    float acc[16];
    #pragma unroll
    for (int c = 0; c < 16; c++) acc[c] = 0.f;
    #pragma unroll
    for (int k = 0; k < 7; k++) {
        float xv = xs[t + k];
        #pragma unroll
        for (int c = 0; c < 16; c++) acc[c] += xv * ws[k*C0 + cb + c];
    }
    uint4 o[2];
    __nv_bfloat162* ob = (__nv_bfloat162*)o;
    #pragma unroll
    for (int j = 0; j < 8; j++) {
        float f0 = fmaxf(acc[2*j]   * ss[cb+2*j]   + bs[cb+2*j],   0.f);
        float f1 = fmaxf(acc[2*j+1] * ss[cb+2*j+1] + bs[cb+2*j+1], 0.f);
        ob[j] = __floats2bfloat162_rn(f0, f1);
    }
    __nv_bfloat16* dst = &d_h1b[(n*TT + t)*C0 + cb];
    *(uint4*)dst = o[0];
    *(uint4*)(dst + 8) = o[1];
}

// ---------------- bf16 gather-aggregate helpers ----------------
__device__ __forceinline__ void acc_row8(float* a, const __nv_bfloat16* p, float w) {
    uint4 v = *(const uint4*)p;
    const __nv_bfloat162* b = (const __nv_bfloat162*)&v;
    #pragma unroll
    for (int j = 0; j < 4; j++) {
        float2 f = __bfloat1622float2(b[j]);
        a[2*j]   += w * f.x;
        a[2*j+1] += w * f.y;
    }
}
__device__ __forceinline__ void store_row8(__nv_bfloat16* p, const float* a) {
    uint4 o;
    __nv_bfloat162* b = (__nv_bfloat162*)&o;
    #pragma unroll
    for (int j = 0; j < 4; j++) b[j] = __floats2bfloat162_rn(a[2*j], a[2*j+1]);
    *(uint4*)p = o;
}

// ---------------- 4: agg1 (bf16): rows of 2048 ----------------
__global__ void k_agg1b() {
    int node = blockIdx.x;
    int off  = threadIdx.x * 8;      // 256 threads * 8
    float di = d_dinv[node];
    float a[8] = {0,0,0,0,0,0,0,0};
    acc_row8(a, d_h1b + (size_t)node*2048 + off, di*di);
    int e0 = d_rowstart[node], e1 = d_rowstart[node+1];
    for (int e = e0; e < e1; e++) {
        int s = d_csrsrc[e];
        acc_row8(a, d_h1b + (size_t)s*2048 + off, di * d_dinv[s]);
    }
    store_row8(d_a1b + (size_t)node*2048 + off, a);
}

// ---------------- 6: agg2 (bf16): rows of 8192, grid.y=4 ----------------
__global__ void k_agg2b() {
    int node = blockIdx.x;
    int off  = blockIdx.y*2048 + threadIdx.x * 8;
    float di = d_dinv[node];
    float a[8] = {0,0,0,0,0,0,0,0};
    acc_row8(a, d_h2b + (size_t)node*8192 + off, di*di);
    int e0 = d_rowstart[node], e1 = d_rowstart[node+1];
    for (int e = e0; e < e1; e++) {
        int s = d_csrsrc[e];
        acc_row8(a, d_h2b + (size_t)s*8192 + off, di * d_dinv[s]);
    }
    store_row8(d_a2b + (size_t)node*8192 + off, a);
}

// ---------------- bf16 mma macro ----------------
#define MMA_BF16(acc, A0, A1, A2, A3, B0, B1)                                   \
    asm volatile(                                                               \
        "mma.sync.aligned.m16n8k16.row.col.f32.bf16.bf16.f32 "                  \
        "{%0,%1,%2,%3}, {%4,%5,%6,%7}, {%8,%9}, {%0,%1,%2,%3};"                 \
        : "+f"(acc[0]), "+f"(acc[1]), "+f"(acc[2]), "+f"(acc[3])                \
        : "r"(A0), "r"(A1), "r"(A2), "r"(A3), "r"(B0), "r"(B1))

// ---------------- 5: gcn1 matmul bf16 mma: (131072,32)@(32,128)+bias+relu -> bf16 -----
__global__ void __launch_bounds__(256) k_mm1b(const float* __restrict__ bias) {
    __shared__ __nv_bfloat16 As[128*40];
    __shared__ __nv_bfloat16 Bs[128*40];
    int tid = threadIdx.x;
    int wid = tid >> 5, lane = tid & 31;
    int g = lane >> 2, tg = lane & 3;
    int rowbase = blockIdx.x * 128;
    int mrow = wid * 16;

    float acc[16][4];
    #pragma unroll
    for (int nt = 0; nt < 16; nt++) {
        int c = nt*8 + 2*tg;
        float b0 = bias[c], b1 = bias[c+1];
        acc[nt][0] = b0; acc[nt][1] = b1; acc[nt][2] = b0; acc[nt][3] = b1;
    }
    #pragma unroll
    for (int i = tid; i < 512; i += 256) {
        int r = i >> 2, k8 = (i & 3) * 8;
        *(uint4*)&As[r*40 + k8] = *(const uint4*)&d_a1b[(size_t)(rowbase + r)*C0 + k8];
    }
    #pragma unroll
    for (int i = tid; i < 512; i += 256) {
        int r = i >> 2, k8 = (i & 3) * 8;
        *(uint4*)&Bs[r*40 + k8] = *(const uint4*)&d_w1tb[r*C0 + k8];
    }
    __syncthreads();
    #pragma unroll
    for (int ks = 0; ks < 32; ks += 16) {
        uint32_t a0 = *(const uint32_t*)&As[(mrow+g  )*40 + ks + 2*tg];
        uint32_t a1 = *(const uint32_t*)&As[(mrow+g+8)*40 + ks + 2*tg];
        uint32_t a2 = *(const uint32_t*)&As[(mrow+g  )*40 + ks + 2*tg + 8];
        uint32_t a3 = *(const uint32_t*)&As[(mrow+g+8)*40 + ks + 2*tg + 8];
        #pragma unroll
        for (int nt = 0; nt < 16; nt++) {
            uint32_t b0 = *(const uint32_t*)&Bs[(nt*8+g)*40 + ks + 2*tg];
            uint32_t b1 = *(const uint32_t*)&Bs[(nt*8+g)*40 + ks + 2*tg + 8];
            MMA_BF16(acc[nt], a0, a1, a2, a3, b0, b1);
        }
    }
    int row0 = rowbase + mrow + g;
    int row1 = row0 + 8;
    #pragma unroll
    for (int nt = 0; nt < 16; nt++) {
        int c = nt*8 + 2*tg;
        *(__nv_bfloat162*)&d_h2b[(size_t)row0*EMB + c] =
            __floats2bfloat162_rn(fmaxf(acc[nt][0], 0.f), fmaxf(acc[nt][1], 0.f));
        *(__nv_bfloat162*)&d_h2b[(size_t)row1*EMB + c] =
            __floats2bfloat162_rn(fmaxf(acc[nt][2], 0.f), fmaxf(acc[nt][3], 0.f));
    }
}

// ---------------- 7: gcn2 matmul bf16 mma: (131072,128)@(128,128)+bias+relu -> bf16 ---
__global__ void __launch_bounds__(256) k_mm2b(const float* __restrict__ bias) {
    __shared__ __nv_bfloat16 As[128*40];
    __shared__ __nv_bfloat16 Bs[128*40];
    int tid = threadIdx.x;
    int wid = tid >> 5, lane = tid & 31;
    int g = lane >> 2, tg = lane & 3;
    int rowbase = blockIdx.x * 128;
    int mrow = wid * 16;

    float acc[16][4];
    #pragma unroll
    for (int nt = 0; nt < 16; nt++) {
        int c = nt*8 + 2*tg;
        float b0 = bias[c], b1 = bias[c+1];
        acc[nt][0] = b0; acc[nt][1] = b1; acc[nt][2] = b0; acc[nt][3] = b1;
    }
    for (int kc = 0; kc < 4; kc++) {
        #pragma unroll
        for (int i = tid; i < 512; i += 256) {
            int r = i >> 2, k8 = (i & 3) * 8;
            *(uint4*)&As[r*40 + k8] =
                *(const uint4*)&d_a2b[(size_t)(rowbase + r)*EMB + kc*32 + k8];
        }
        #pragma unroll
        for (int i = tid; i < 512; i += 256) {
            int r = i >> 2, k8 = (i & 3) * 8;
            *(uint4*)&Bs[r*40 + k8] = *(const uint4*)&d_w2tb[r*EMB + kc*32 + k8];
        }
        __syncthreads();
        #pragma unroll
        for (int ks = 0; ks < 32; ks += 16) {
            uint32_t a0 = *(const uint32_t*)&As[(mrow+g  )*40 + ks + 2*tg];
            uint32_t a1 = *(const uint32_t*)&As[(mrow+g+8)*40 + ks + 2*tg];
            uint32_t a2 = *(const uint32_t*)&As[(mrow+g  )*40 + ks + 2*tg + 8];
            uint32_t a3 = *(const uint32_t*)&As[(mrow+g+8)*40 + ks + 2*tg + 8];
            #pragma unroll
            for (int nt = 0; nt < 16; nt++) {
                uint32_t b0 = *(const uint32_t*)&Bs[(nt*8+g)*40 + ks + 2*tg];
                uint32_t b1 = *(const uint32_t*)&Bs[(nt*8+g)*40 + ks + 2*tg + 8];
                MMA_BF16(acc[nt], a0, a1, a2, a3, b0, b1);
            }
        }
        __syncthreads();
    }
    int row0 = rowbase + mrow + g;
    int row1 = row0 + 8;
    #pragma unroll
    for (int nt = 0; nt < 16; nt++) {
        int c = nt*8 + 2*tg;
        *(__nv_bfloat162*)&d_h2b[(size_t)row0*EMB + c] =
            __floats2bfloat162_rn(fmaxf(acc[nt][0], 0.f), fmaxf(acc[nt][1], 0.f));
        *(__nv_bfloat162*)&d_h2b[(size_t)row1*EMB + c] =
            __floats2bfloat162_rn(fmaxf(acc[nt][2], 0.f), fmaxf(acc[nt][3], 0.f));
    }
}

// ---------------- 8: conv2+bn2+pool+relu GEMM, fused graph-pool epilogue --------------
// 8 nodes/block -> M=112 (pad 128); N=64; K = 20 chunks of 64 (u, ci-half).
// Epilogue: atomicAdd relu(acc) into d_gp[batch[n]*896 + p*64 + c].
__global__ void __launch_bounds__(256) k_conv2b(const int* __restrict__ batch) {
    __shared__ __nv_bfloat16 As[128*72];   // 18KB
    __shared__ __nv_bfloat16 Bs[64*72];    // 9KB
    int tid = threadIdx.x;
    int wid = tid >> 5, lane = tid & 31;
    int g = lane >> 2, tg = lane & 3;
    int n0 = blockIdx.x * 8;
    int mrow = wid * 16;

    float acc[8][4];
    #pragma unroll
    for (int nt = 0; nt < 8; nt++) {
        int c = nt*8 + 2*tg;
        float b0 = d_beff2[c], b1 = d_beff2[c+1];
        acc[nt][0] = b0; acc[nt][1] = b1; acc[nt][2] = b0; acc[nt][3] = b1;
    }
    for (int u = 0; u < 10; u++) {
        for (int h = 0; h < 2; h++) {
            // A: 128 rows x 64 k (row = nl*14+p)
            #pragma unroll
            for (int i = tid; i < 1024; i += 256) {
                int r = i >> 3, k8 = (i & 7) * 8;
                uint4 v = make_uint4(0u, 0u, 0u, 0u);
                if (r < 112) {
                    int nl = r / 14, p = r - nl*14;
                    v = *(const uint4*)
                        &d_h2b[(size_t)((n0+nl)*TT + 4*p + u)*EMB + h*64 + k8];
                }
                *(uint4*)&As[r*72 + k8] = v;
            }
            // B: 64 c x 64 k
            #pragma unroll
            for (int i = tid; i < 512; i += 256) {
                int c = i >> 3, k8 = (i & 7) * 8;
                *(uint4*)&Bs[c*72 + k8] =
                    *(const uint4*)&d_weff2tb[(size_t)c*1280 + u*128 + h*64 + k8];
            }
            __syncthreads();
            #pragma unroll
            for (int ks = 0; ks < 64; ks += 16) {
                uint32_t a0 = *(const uint32_t*)&As[(mrow+g  )*72 + ks + 2*tg];
                uint32_t a1 = *(const uint32_t*)&As[(mrow+g+8)*72 + ks + 2*tg];
                uint32_t a2 = *(const uint32_t*)&As[(mrow+g  )*72 + ks + 2*tg + 8];
                uint32_t a3 = *(const uint32_t*)&As[(mrow+g+8)*72 + ks + 2*tg + 8];
                #pragma unroll
                for (int nt = 0; nt < 8; nt++) {
                    uint32_t b0 = *(const uint32_t*)&Bs[(nt*8+g)*72 + ks + 2*tg];
                    uint32_t b1 = *(const uint32_t*)&Bs[(nt*8+g)*72 + ks + 2*tg + 8];
                    MMA_BF16(acc[nt], a0, a1, a2, a3, b0, b1);
                }
            }
            __syncthreads();
        }
    }
    // fused graph pool: rows >= 112 are padding (warp 7 entirely)
    int r0 = mrow + g;
    if (r0 < 112) {
        int nl0 = r0 / 14, p0 = r0 - nl0*14;
        int base0 = batch[n0 + nl0]*(14*C1) + p0*C1;
        int r1 = r0 + 8;
        int nl1 = r1 / 14, p1 = r1 - nl1*14;
        int base1 = batch[n0 + nl1]*(14*C1) + p1*C1;
        #pragma unroll
        for (int nt = 0; nt < 8; nt++) {
            int c = nt*8 + 2*tg;
            atomicAdd(&d_gp[base0 + c],     fmaxf(acc[nt][0], 0.f));
            atomicAdd(&d_gp[base0 + c + 1], fmaxf(acc[nt][1], 0.f));
            atomicAdd(&d_gp[base1 + c],     fmaxf(acc[nt][2], 0.f));
            atomicAdd(&d_gp[base1 + c + 1], fmaxf(acc[nt][3], 0.f));
        }
    }
}

// ---------------- 9: conv3+bn3+pool+relu + dense + log_softmax ----------------
__global__ void k_final(const float* __restrict__ dw, const float* __restrict__ db,
                        float* __restrict__ out) {
    __shared__ float gin[14*C1];
    __shared__ float flat[128];
    __shared__ float lg[4];
    int b = blockIdx.x, tid = threadIdx.x;     // 128 threads
    float inv = 1.f / d_counts[b];
    for (int i = tid; i < 14*C1; i += 128) gin[i] = d_gp[b*14*C1 + i] * inv;
    __syncthreads();
    int p = tid >> 6, c = tid & 63;
    float acc = d_beff3[c];
    for (int u = 0; u < 10; u++)
        for (int ci = 0; ci < C2; ci++)
            acc += gin[(4*p + u)*C2 + ci] * d_weff3[(u*C2 + ci)*C2 + c];
    flat[p*64 + c] = fmaxf(acc, 0.f);
    __syncthreads();
    if (tid < 4) {
        float a = db[tid];
        for (int i = 0; i < 128; i++) a += flat[i] * dw[i*4 + tid];
        lg[tid] = a;
    }
    __syncthreads();
    if (tid == 0) {
        float m = fmaxf(fmaxf(lg[0], lg[1]), fmaxf(lg[2], lg[3]));
        float se = expf(lg[0]-m) + expf(lg[1]-m) + expf(lg[2]-m) + expf(lg[3]-m);
        float lse = logf(se) + m;
        for (int j = 0; j < 4; j++) out[b*4 + j] = lg[j] - lse;
    }
}

// ---------------- launcher ----------------
extern "C" void kernel_launch(void* const* d_in, const int* in_sizes, int n_in,
                              void* d_out, int out_size) {
    const float* x       = (const float*)d_in[0];
    const int*   edge    = (const int*)d_in[1];
    const int*   batch   = (const int*)d_in[2];
    const float* conv1_w = (const float*)d_in[3];
    const float* bn1_g   = (const float*)d_in[4];
    const float* bn1_b   = (const float*)d_in[5];
    const float* bn1_m   = (const float*)d_in[6];
    const float* bn1_v   = (const float*)d_in[7];
    const float* gcn1_w  = (const float*)d_in[8];
    const float* gcn1_b  = (const float*)d_in[9];
    const float* gcn2_w  = (const float*)d_in[10];
    const float* gcn2_b  = (const float*)d_in[11];
    const float* conv2_w = (const float*)d_in[12];
    const float* bn2_g   = (const float*)d_in[13];
    const float* bn2_b   = (const float*)d_in[14];
    const float* bn2_m   = (const float*)d_in[15];
    const float* bn2_v   = (const float*)d_in[16];
    const float* conv3_w = (const float*)d_in[17];
    const float* bn3_g   = (const float*)d_in[18];
    const float* bn3_b   = (const float*)d_in[19];
    const float* bn3_m   = (const float*)d_in[20];
    const float* bn3_v   = (const float*)d_in[21];
    const float* dense_w = (const float*)d_in[22];
    const float* dense_b = (const float*)d_in[23];
    float* out = (float*)d_out;

    k_graph<<<1, 1024>>>(edge);
    k_prep<<<320, 256>>>(batch, bn1_g, bn1_b, bn1_m, bn1_v,
                         gcn1_w, gcn2_w,
                         conv2_w, bn2_g, bn2_b, bn2_m, bn2_v,
                         conv3_w, bn3_g, bn3_b, bn3_m, bn3_v);
    k_conv1<<<NN, 128>>>(x, conv1_w);
    k_agg1b<<<NN, 256>>>();
    k_mm1b<<<1024, 256>>>(gcn1_b);
    k_agg2b<<<dim3(NN, 4), 256>>>();
    k_mm2b<<<1024, 256>>>(gcn2_b);
    k_conv2b<<<256, 256>>>(batch);
    k_final<<<BB, 128>>>(dense_w, dense_b, out);
}

// round 7
// speedup vs baseline: 4.4699x; 1.0453x over previous
#include <cuda_runtime.h>
#include <cuda_bf16.h>
#include <math.h>
#include <stdint.h>

#define NN  2048
#define TT  64
#define EE  16384
#define BB  64
#define C0  32
#define EMB 128
#define C1  64
#define C2  64
#define EPSB 1e-5f

// ---------------- scratch (device globals; BSS -> zero at load) ----------------
__device__ __nv_bfloat16 d_h1b[NN*TT*C0];    // conv1 out (8MB)
__device__ __nv_bfloat16 d_a1b[NN*TT*C0];    // agg1 out  (8MB)
__device__ __nv_bfloat16 d_h2b[NN*TT*EMB];   // gcn1/gcn2 out (32MB)
__device__ __nv_bfloat16 d_a2b[NN*TT*EMB];   // agg2 out  (32MB)
__device__ float d_gp[BB*14*C1];             // INVARIANT: zero at entry (k_final re-zeros)
__device__ int   d_rowcnt[NN];               // INVARIANT: zero at entry (k_scan re-zeros)
__device__ int   d_rowstart[NN+1];
__device__ int   d_cursor[NN];
__device__ int   d_csrsrc[EE];
__device__ float d_dinv[NN];
__device__ __nv_bfloat16 d_w1tb[EMB*C0];       // gcn1 W transposed [n][k] bf16
__device__ __nv_bfloat16 d_w2tb[EMB*EMB];      // gcn2 W transposed [n][k] bf16
__device__ __nv_bfloat16 d_weff2tb[C1*1280];   // conv2 eff W transposed [c][u*128+ci] bf16
__device__ float d_beff2[C1];
__device__ float d_weff3[10*C2*C2];
__device__ float d_beff3[C2];

// ---------------- 1: prep (weight folds + parallel degree count) ----------------
__global__ void k_prep(const int* __restrict__ edge,
                       const float* __restrict__ w1, const float* __restrict__ wg2,
                       const float* __restrict__ w2, const float* __restrict__ g2,
                       const float* __restrict__ b2, const float* __restrict__ m2,
                       const float* __restrict__ v2,
                       const float* __restrict__ w3, const float* __restrict__ g3,
                       const float* __restrict__ b3, const float* __restrict__ m3,
                       const float* __restrict__ v3) {
    int i = blockIdx.x * blockDim.x + threadIdx.x;
    if (i < EE) atomicAdd(&d_rowcnt[edge[EE + i]], 1);   // d_rowcnt zero by invariant
    if (i < C1) { float s = g2[i]*rsqrtf(v2[i]+EPSB); d_beff2[i]=b2[i]-m2[i]*s; }
    if (i < C2) { float s = g3[i]*rsqrtf(v3[i]+EPSB); d_beff3[i]=b3[i]-m3[i]*s; }
    if (i < EMB*C0) {
        int n = i >> 5, k = i & 31;
        d_w1tb[i] = __float2bfloat16(w1[k*EMB + n]);
    }
    if (i < EMB*EMB) {
        int n = i >> 7, k = i & 127;
        d_w2tb[i] = __float2bfloat16(wg2[k*EMB + n]);
    }
    if (i < C1*1280) {
        int c = i / 1280, kk = i - c*1280;
        int u = kk >> 7, ci = kk & 127;
        float s = g2[c]*rsqrtf(v2[c]+EPSB);
        int klo = u-3; if (klo < 0) klo = 0;
        int khi = u < 6 ? u : 6;
        float acc = 0.f;
        for (int k = klo; k <= khi; k++) acc += w2[(k*EMB+ci)*C1 + c];
        d_weff2tb[i] = __float2bfloat16(acc * s * 0.25f);
    }
    if (i < 10*C2*C2) {
        int c = i % C2; int ci = (i / C2) % C2; int u = i / (C2*C2);
        float s = g3[c]*rsqrtf(v3[c]+EPSB);
        int klo = u-3; if (klo < 0) klo = 0;
        int khi = u < 6 ? u : 6;
        float acc = 0.f;
        for (int k = klo; k <= khi; k++) acc += w3[(k*C2+ci)*C2 + c];
        d_weff3[i] = acc * s * 0.25f;
    }
}

// ---------------- 2: scan only (1 block; reads rowcnt, restores its zero) ------------
__global__ void __launch_bounds__(1024) k_scan() {
    __shared__ int sa[NN], sb[NN];
    int t = threadIdx.x;
    int c0 = d_rowcnt[t], c1 = d_rowcnt[t+1024];
    sa[t] = c0; sa[t+1024] = c1;
    d_rowcnt[t] = 0; d_rowcnt[t+1024] = 0;           // restore invariant
    d_dinv[t]      = rsqrtf((float)(c0 + 1));
    d_dinv[t+1024] = rsqrtf((float)(c1 + 1));
    __syncthreads();
    int* cur = sa; int* nxt = sb;
    for (int off = 1; off < NN; off <<= 1) {
        for (int j = t; j < NN; j += 1024) {
            int v = cur[j];
            if (j >= off) v += cur[j-off];
            nxt[j] = v;
        }
        __syncthreads();
        int* tmp = cur; cur = nxt; nxt = tmp;
    }
    for (int j = t; j < NN; j += 1024) {
        int excl = (j == 0) ? 0 : cur[j-1];
        d_rowstart[j] = excl;
        d_cursor[j]   = excl;
        if (j == NN-1) d_rowstart[NN] = cur[NN-1];
    }
}

// ---------------- 3: conv1(+inline bn1 fold) for blocks<NN; CSR scatter on the rest --
__global__ void __launch_bounds__(128) k_conv1sc(const float* __restrict__ x,
                                                const float* __restrict__ w,
                                                const float* __restrict__ g1,
                                                const float* __restrict__ b1,
                                                const float* __restrict__ m1,
                                                const float* __restrict__ v1,
                                                const int* __restrict__ edge) {
    int blk = blockIdx.x, tid = threadIdx.x;
    if (blk >= NN) {
        // 32 scatter blocks x 128 threads
        for (int e = (blk - NN)*128 + tid; e < EE; e += 32*128) {
            int dd = edge[EE + e];
            int pos = atomicAdd(&d_cursor[dd], 1);
            d_csrsrc[pos] = edge[e];
        }
        return;
    }
    __shared__ float xs[TT + 6];   // zero-padded halo
    __shared__ float ws[7*C0];
    __shared__ float ss[C0], bs[C0];
    int n = blk;
    if (tid < TT) xs[tid + 3] = x[n*TT + tid];
    if (tid < 3)  { xs[tid] = 0.f; xs[TT + 3 + tid] = 0.f; }
    for (int i = tid; i < 7*C0; i += 128) ws[i] = w[i];
    if (tid < C0) {
        float s = g1[tid]*rsqrtf(v1[tid]+EPSB);
        ss[tid] = s; bs[tid] = b1[tid] - m1[tid]*s;
    }
    __syncthreads();
    int t = tid >> 1, cb = (tid & 1) * 16;
    float acc[16];
    #pragma unroll
    for (int c = 0; c < 16; c++) acc[c] = 0.f;
    #pragma unroll
    for (int k = 0; k < 7; k++) {
        float xv = xs[t + k];
        #pragma unroll
        for (int c = 0; c < 16; c++) acc[c] += xv * ws[k*C0 + cb + c];
    }
    uint4 o[2];
    __nv_bfloat162* ob = (__nv_bfloat162*)o;
    #pragma unroll
    for (int j = 0; j < 8; j++) {
        float f0 = fmaxf(acc[2*j]   * ss[cb+2*j]   + bs[cb+2*j],   0.f);
        float f1 = fmaxf(acc[2*j+1] * ss[cb+2*j+1] + bs[cb+2*j+1], 0.f);
        ob[j] = __floats2bfloat162_rn(f0, f1);
    }
    __nv_bfloat16* dst = &d_h1b[(n*TT + t)*C0 + cb];
    *(uint4*)dst = o[0];
    *(uint4*)(dst + 8) = o[1];
}

// ---------------- bf16 gather-aggregate helpers ----------------
__device__ __forceinline__ void acc_row8(float* a, const __nv_bfloat16* p, float w) {
    uint4 v = *(const uint4*)p;
    const __nv_bfloat162* b = (const __nv_bfloat162*)&v;
    #pragma unroll
    for (int j = 0; j < 4; j++) {
        float2 f = __bfloat1622float2(b[j]);
        a[2*j]   += w * f.x;
        a[2*j+1] += w * f.y;
    }
}
__device__ __forceinline__ void store_row8(__nv_bfloat16* p, const float* a, float sc) {
    uint4 o;
    __nv_bfloat162* b = (__nv_bfloat162*)&o;
    #pragma unroll
    for (int j = 0; j < 4; j++) b[j] = __floats2bfloat162_rn(a[2*j]*sc, a[2*j+1]*sc);
    *(uint4*)p = o;
}

// ---------------- 4: agg1 (bf16): rows of 2048; staged metadata; di factored ---------
__global__ void __launch_bounds__(256) k_agg1b() {
    __shared__ int   ssrc[32];
    __shared__ float sw[32];
    int node = blockIdx.x;
    int off  = threadIdx.x * 8;
    float di = d_dinv[node];
    float a[8] = {0,0,0,0,0,0,0,0};
    acc_row8(a, d_h1b + (size_t)node*2048 + off, di);   // self: weight di (x di later)
    int e0 = d_rowstart[node], e1 = d_rowstart[node+1];
    for (int eb = e0; eb < e1; eb += 32) {
        int m = e1 - eb; if (m > 32) m = 32;
        __syncthreads();
        if (threadIdx.x < m) {
            int s = d_csrsrc[eb + threadIdx.x];
            ssrc[threadIdx.x] = s;
            sw[threadIdx.x]   = d_dinv[s];
        }
        __syncthreads();
        for (int j = 0; j < m; j++)
            acc_row8(a, d_h1b + (size_t)ssrc[j]*2048 + off, sw[j]);
    }
    store_row8(d_a1b + (size_t)node*2048 + off, a, di);
}

// ---------------- 6: agg2 (bf16): rows of 8192, grid.y=4; staged metadata ------------
__global__ void __launch_bounds__(256) k_agg2b() {
    __shared__ int   ssrc[32];
    __shared__ float sw[32];
    int node = blockIdx.x;
    int off  = blockIdx.y*2048 + threadIdx.x * 8;
    float di = d_dinv[node];
    float a[8] = {0,0,0,0,0,0,0,0};
    acc_row8(a, d_h2b + (size_t)node*8192 + off, di);
    int e0 = d_rowstart[node], e1 = d_rowstart[node+1];
    for (int eb = e0; eb < e1; eb += 32) {
        int m = e1 - eb; if (m > 32) m = 32;
        __syncthreads();
        if (threadIdx.x < m) {
            int s = d_csrsrc[eb + threadIdx.x];
            ssrc[threadIdx.x] = s;
            sw[threadIdx.x]   = d_dinv[s];
        }
        __syncthreads();
        for (int j = 0; j < m; j++)
            acc_row8(a, d_h2b + (size_t)ssrc[j]*8192 + off, sw[j]);
    }
    store_row8(d_a2b + (size_t)node*8192 + off, a, di);
}

// ---------------- bf16 mma macro ----------------
#define MMA_BF16(acc, A0, A1, A2, A3, B0, B1)                                   \
    asm volatile(                                                               \
        "mma.sync.aligned.m16n8k16.row.col.f32.bf16.bf16.f32 "                  \
        "{%0,%1,%2,%3}, {%4,%5,%6,%7}, {%8,%9}, {%0,%1,%2,%3};"                 \
        : "+f"(acc[0]), "+f"(acc[1]), "+f"(acc[2]), "+f"(acc[3])                \
        : "r"(A0), "r"(A1), "r"(A2), "r"(A3), "r"(B0), "r"(B1))

// ---------------- 5: gcn1 matmul bf16 mma: (131072,32)@(32,128)+bias+relu -> bf16 -----
__global__ void __launch_bounds__(256) k_mm1b(const float* __restrict__ bias) {
    __shared__ __nv_bfloat16 As[128*40];
    __shared__ __nv_bfloat16 Bs[128*40];
    int tid = threadIdx.x;
    int wid = tid >> 5, lane = tid & 31;
    int g = lane >> 2, tg = lane & 3;
    int rowbase = blockIdx.x * 128;
    int mrow = wid * 16;

    float acc[16][4];
    #pragma unroll
    for (int nt = 0; nt < 16; nt++) {
        int c = nt*8 + 2*tg;
        float b0 = bias[c], b1 = bias[c+1];
        acc[nt][0] = b0; acc[nt][1] = b1; acc[nt][2] = b0; acc[nt][3] = b1;
    }
    #pragma unroll
    for (int i = tid; i < 512; i += 256) {
        int r = i >> 2, k8 = (i & 3) * 8;
        *(uint4*)&As[r*40 + k8] = *(const uint4*)&d_a1b[(size_t)(rowbase + r)*C0 + k8];
    }
    #pragma unroll
    for (int i = tid; i < 512; i += 256) {
        int r = i >> 2, k8 = (i & 3) * 8;
        *(uint4*)&Bs[r*40 + k8] = *(const uint4*)&d_w1tb[r*C0 + k8];
    }
    __syncthreads();
    #pragma unroll
    for (int ks = 0; ks < 32; ks += 16) {
        uint32_t a0 = *(const uint32_t*)&As[(mrow+g  )*40 + ks + 2*tg];
        uint32_t a1 = *(const uint32_t*)&As[(mrow+g+8)*40 + ks + 2*tg];
        uint32_t a2 = *(const uint32_t*)&As[(mrow+g  )*40 + ks + 2*tg + 8];
        uint32_t a3 = *(const uint32_t*)&As[(mrow+g+8)*40 + ks + 2*tg + 8];
        #pragma unroll
        for (int nt = 0; nt < 16; nt++) {
            uint32_t b0 = *(const uint32_t*)&Bs[(nt*8+g)*40 + ks + 2*tg];
            uint32_t b1 = *(const uint32_t*)&Bs[(nt*8+g)*40 + ks + 2*tg + 8];
            MMA_BF16(acc[nt], a0, a1, a2, a3, b0, b1);
        }
    }
    int row0 = rowbase + mrow + g;
    int row1 = row0 + 8;
    #pragma unroll
    for (int nt = 0; nt < 16; nt++) {
        int c = nt*8 + 2*tg;
        *(__nv_bfloat162*)&d_h2b[(size_t)row0*EMB + c] =
            __floats2bfloat162_rn(fmaxf(acc[nt][0], 0.f), fmaxf(acc[nt][1], 0.f));
        *(__nv_bfloat162*)&d_h2b[(size_t)row1*EMB + c] =
            __floats2bfloat162_rn(fmaxf(acc[nt][2], 0.f), fmaxf(acc[nt][3], 0.f));
    }
}

// ---------------- 7: gcn2 matmul bf16 mma: (131072,128)@(128,128)+bias+relu -> bf16 ---
__global__ void __launch_bounds__(256) k_mm2b(const float* __restrict__ bias) {
    __shared__ __nv_bfloat16 As[128*40];
    __shared__ __nv_bfloat16 Bs[128*40];
    int tid = threadIdx.x;
    int wid = tid >> 5, lane = tid & 31;
    int g = lane >> 2, tg = lane & 3;
    int rowbase = blockIdx.x * 128;
    int mrow = wid * 16;

    float acc[16][4];
    #pragma unroll
    for (int nt = 0; nt < 16; nt++) {
        int c = nt*8 + 2*tg;
        float b0 = bias[c], b1 = bias[c+1];
        acc[nt][0] = b0; acc[nt][1] = b1; acc[nt][2] = b0; acc[nt][3] = b1;
    }
    for (int kc = 0; kc < 4; kc++) {
        #pragma unroll
        for (int i = tid; i < 512; i += 256) {
            int r = i >> 2, k8 = (i & 3) * 8;
            *(uint4*)&As[r*40 + k8] =
                *(const uint4*)&d_a2b[(size_t)(rowbase + r)*EMB + kc*32 + k8];
        }
        #pragma unroll
        for (int i = tid; i < 512; i += 256) {
            int r = i >> 2, k8 = (i & 3) * 8;
            *(uint4*)&Bs[r*40 + k8] = *(const uint4*)&d_w2tb[r*EMB + kc*32 + k8];
        }
        __syncthreads();
        #pragma unroll
        for (int ks = 0; ks < 32; ks += 16) {
            uint32_t a0 = *(const uint32_t*)&As[(mrow+g  )*40 + ks + 2*tg];
            uint32_t a1 = *(const uint32_t*)&As[(mrow+g+8)*40 + ks + 2*tg];
            uint32_t a2 = *(const uint32_t*)&As[(mrow+g  )*40 + ks + 2*tg + 8];
            uint32_t a3 = *(const uint32_t*)&As[(mrow+g+8)*40 + ks + 2*tg + 8];
            #pragma unroll
            for (int nt = 0; nt < 16; nt++) {
                uint32_t b0 = *(const uint32_t*)&Bs[(nt*8+g)*40 + ks + 2*tg];
                uint32_t b1 = *(const uint32_t*)&Bs[(nt*8+g)*40 + ks + 2*tg + 8];
                MMA_BF16(acc[nt], a0, a1, a2, a3, b0, b1);
            }
        }
        __syncthreads();
    }
    int row0 = rowbase + mrow + g;
    int row1 = row0 + 8;
    #pragma unroll
    for (int nt = 0; nt < 16; nt++) {
        int c = nt*8 + 2*tg;
        *(__nv_bfloat162*)&d_h2b[(size_t)row0*EMB + c] =
            __floats2bfloat162_rn(fmaxf(acc[nt][0], 0.f), fmaxf(acc[nt][1], 0.f));
        *(__nv_bfloat162*)&d_h2b[(size_t)row1*EMB + c] =
            __floats2bfloat162_rn(fmaxf(acc[nt][2], 0.f), fmaxf(acc[nt][3], 0.f));
    }
}

// ---------------- 8: conv2+bn2+pool+relu GEMM, fused graph-pool epilogue --------------
__global__ void __launch_bounds__(256) k_conv2b(const int* __restrict__ batch) {
    __shared__ __nv_bfloat16 As[128*72];   // 18KB
    __shared__ __nv_bfloat16 Bs[64*72];    // 9KB
    int tid = threadIdx.x;
    int wid = tid >> 5, lane = tid & 31;
    int g = lane >> 2, tg = lane & 3;
    int n0 = blockIdx.x * 8;
    int mrow = wid * 16;

    float acc[8][4];
    #pragma unroll
    for (int nt = 0; nt < 8; nt++) {
        int c = nt*8 + 2*tg;
        float b0 = d_beff2[c], b1 = d_beff2[c+1];
        acc[nt][0] = b0; acc[nt][1] = b1; acc[nt][2] = b0; acc[nt][3] = b1;
    }
    for (int u = 0; u < 10; u++) {
        for (int h = 0; h < 2; h++) {
            #pragma unroll
            for (int i = tid; i < 1024; i += 256) {
                int r = i >> 3, k8 = (i & 7) * 8;
                uint4 v = make_uint4(0u, 0u, 0u, 0u);
                if (r < 112) {
                    int nl = r / 14, p = r - nl*14;
                    v = *(const uint4*)
                        &d_h2b[(size_t)((n0+nl)*TT + 4*p + u)*EMB + h*64 + k8];
                }
                *(uint4*)&As[r*72 + k8] = v;
            }
            #pragma unroll
            for (int i = tid; i < 512; i += 256) {
                int c = i >> 3, k8 = (i & 7) * 8;
                *(uint4*)&Bs[c*72 + k8] =
                    *(const uint4*)&d_weff2tb[(size_t)c*1280 + u*128 + h*64 + k8];
            }
            __syncthreads();
            #pragma unroll
            for (int ks = 0; ks < 64; ks += 16) {
                uint32_t a0 = *(const uint32_t*)&As[(mrow+g  )*72 + ks + 2*tg];
                uint32_t a1 = *(const uint32_t*)&As[(mrow+g+8)*72 + ks + 2*tg];
                uint32_t a2 = *(const uint32_t*)&As[(mrow+g  )*72 + ks + 2*tg + 8];
                uint32_t a3 = *(const uint32_t*)&As[(mrow+g+8)*72 + ks + 2*tg + 8];
                #pragma unroll
                for (int nt = 0; nt < 8; nt++) {
                    uint32_t b0 = *(const uint32_t*)&Bs[(nt*8+g)*72 + ks + 2*tg];
                    uint32_t b1 = *(const uint32_t*)&Bs[(nt*8+g)*72 + ks + 2*tg + 8];
                    MMA_BF16(acc[nt], a0, a1, a2, a3, b0, b1);
                }
            }
            __syncthreads();
        }
    }
    int r0 = mrow + g;
    if (r0 < 112) {
        int nl0 = r0 / 14, p0 = r0 - nl0*14;
        int base0 = batch[n0 + nl0]*(14*C1) + p0*C1;
        int r1 = r0 + 8;
        int nl1 = r1 / 14, p1 = r1 - nl1*14;
        int base1 = batch[n0 + nl1]*(14*C1) + p1*C1;
        #pragma unroll
        for (int nt = 0; nt < 8; nt++) {
            int c = nt*8 + 2*tg;
            atomicAdd(&d_gp[base0 + c],     fmaxf(acc[nt][0], 0.f));
            atomicAdd(&d_gp[base0 + c + 1], fmaxf(acc[nt][1], 0.f));
            atomicAdd(&d_gp[base1 + c],     fmaxf(acc[nt][2], 0.f));
            atomicAdd(&d_gp[base1 + c + 1], fmaxf(acc[nt][3], 0.f));
        }
    }
}

// ---------------- 9: conv3+bn3+pool+relu + dense + log_softmax (+restore d_gp zero) ---
__global__ void __launch_bounds__(128) k_final(const int* __restrict__ batch,
                                               const float* __restrict__ dw,
                                               const float* __restrict__ db,
                                               float* __restrict__ out) {
    __shared__ float gin[14*C1];
    __shared__ float flat[128];
    __shared__ float lg[4];
    __shared__ int scount;
    int b = blockIdx.x, tid = threadIdx.x;     // 128 threads
    // local per-graph node count (no global atomics needed)
    if (tid == 0) scount = 0;
    __syncthreads();
    int cnt = 0;
    for (int i = tid; i < NN; i += 128) cnt += (batch[i] == b);
    #pragma unroll
    for (int s = 16; s > 0; s >>= 1) cnt += __shfl_down_sync(0xffffffffu, cnt, s);
    if ((tid & 31) == 0) atomicAdd(&scount, cnt);
    // load pooled sums, then restore the zero invariant on this block's slice
    for (int i = tid; i < 14*C1; i += 128) gin[i] = d_gp[b*14*C1 + i];
    __syncthreads();
    float inv = 1.f / (float)scount;
    for (int i = tid; i < 14*C1; i += 128) d_gp[b*14*C1 + i] = 0.f;
    int p = tid >> 6, c = tid & 63;
    float acc = d_beff3[c];
    for (int u = 0; u < 10; u++)
        for (int ci = 0; ci < C2; ci++)
            acc += gin[(4*p + u)*C2 + ci] * inv * d_weff3[(u*C2 + ci)*C2 + c];
    flat[p*64 + c] = fmaxf(acc, 0.f);
    __syncthreads();
    if (tid < 4) {
        float a = db[tid];
        for (int i = 0; i < 128; i++) a += flat[i] * dw[i*4 + tid];
        lg[tid] = a;
    }
    __syncthreads();
    if (tid == 0) {
        float m = fmaxf(fmaxf(lg[0], lg[1]), fmaxf(lg[2], lg[3]));
        float se = expf(lg[0]-m) + expf(lg[1]-m) + expf(lg[2]-m) + expf(lg[3]-m);
        float lse = logf(se) + m;
        for (int j = 0; j < 4; j++) out[b*4 + j] = lg[j] - lse;
    }
}

// ---------------- launcher ----------------
extern "C" void kernel_launch(void* const* d_in, const int* in_sizes, int n_in,
                              void* d_out, int out_size) {
    const float* x       = (const float*)d_in[0];
    const int*   edge    = (const int*)d_in[1];
    const int*   batch   = (const int*)d_in[2];
    const float* conv1_w = (const float*)d_in[3];
    const float* bn1_g   = (const float*)d_in[4];
    const float* bn1_b   = (const float*)d_in[5];
    const float* bn1_m   = (const float*)d_in[6];
    const float* bn1_v   = (const float*)d_in[7];
    const float* gcn1_w  = (const float*)d_in[8];
    const float* gcn1_b  = (const float*)d_in[9];
    const float* gcn2_w  = (const float*)d_in[10];
    const float* gcn2_b  = (const float*)d_in[11];
    const float* conv2_w = (const float*)d_in[12];
    const float* bn2_g   = (const float*)d_in[13];
    const float* bn2_b   = (const float*)d_in[14];
    const float* bn2_m   = (const float*)d_in[15];
    const float* bn2_v   = (const float*)d_in[16];
    const float* conv3_w = (const float*)d_in[17];
    const float* bn3_g   = (const float*)d_in[18];
    const float* bn3_b   = (const float*)d_in[19];
    const float* bn3_m   = (const float*)d_in[20];
    const float* bn3_v   = (const float*)d_in[21];
    const float* dense_w = (const float*)d_in[22];
    const float* dense_b = (const float*)d_in[23];
    float* out = (float*)d_out;

    k_prep<<<320, 256>>>(edge, gcn1_w, gcn2_w,
                         conv2_w, bn2_g, bn2_b, bn2_m, bn2_v,
                         conv3_w, bn3_g, bn3_b, bn3_m, bn3_v);
    k_scan<<<1, 1024>>>();
    k_conv1sc<<<NN + 32, 128>>>(x, conv1_w, bn1_g, bn1_b, bn1_m, bn1_v, edge);
    k_agg1b<<<NN, 256>>>();
    k_mm1b<<<1024, 256>>>(gcn1_b);
    k_agg2b<<<dim3(NN, 4), 256>>>();
    k_mm2b<<<1024, 256>>>(gcn2_b);
    k_conv2b<<<256, 256>>>(batch);
    k_final<<<BB, 128>>>(batch, dense_w, dense_b, out);
}